// round 2
// baseline (speedup 1.0000x reference)
#include <cuda_runtime.h>
#include <cuda_bf16.h>
#include <math.h>
#include <stdint.h>

#define B_  32768
#define C_  1024
#define CH_ 256
#define RANK_ 16

// ---------------- scratch (device globals; no allocation allowed) ----------
__device__ __nv_bfloat16 g_z [B_ * C_];    // LN output, bf16
__device__ float         g_sa[B_ * CH_];   // raw z@Wd
__device__ __nv_bfloat16 g_u [B_ * CH_];   // GLU output
__device__ __nv_bfloat16 g_p [B_ * CH_];   // gelu(u@W1'+b1')
__device__ __nv_bfloat16 g_q [B_ * CH_];   // p@W23+b23

__device__ __nv_bfloat16 g_Wd [C_ * CH_];
__device__ __nv_bfloat16 g_Wg [C_ * CH_];
__device__ __nv_bfloat16 g_W1 [CH_ * CH_];   // dw-folded
__device__ __nv_bfloat16 g_W23[CH_ * CH_];   // W2@Wv@Wo
__device__ __nv_bfloat16 g_WuE[CH_ * C_];    // Wu(I + Wld Wlu)

__device__ float g_fWvo[CH_ * CH_];
__device__ float g_fW23[CH_ * CH_];
__device__ float g_fT1 [CH_ * RANK_];
__device__ float g_fWuE[CH_ * C_];
__device__ float g_b1p[CH_], g_bvo[CH_], g_b23[CH_], g_t16[RANK_], g_buE[C_];

// ---------------- tiny prep kernels ----------------------------------------
__global__ void k_gemm_naive(const float* __restrict__ A, const float* __restrict__ Bm,
                             const float* __restrict__ addC, float* __restrict__ Cm,
                             int M, int N, int K) {
    int idx = blockIdx.x * blockDim.x + threadIdx.x;
    if (idx >= M * N) return;
    int i = idx / N, j = idx % N;
    float s = addC ? addC[idx] : 0.f;
    for (int k = 0; k < K; k++) s += A[i * K + k] * Bm[k * N + j];
    Cm[idx] = s;
}

__global__ void k_vecmat(const float* __restrict__ v, const float* __restrict__ W,
                         const float* __restrict__ add, float* __restrict__ out,
                         int K, int N) {
    int j = blockIdx.x * blockDim.x + threadIdx.x;
    if (j >= N) return;
    float s = add ? add[j] : 0.f;
    for (int k = 0; k < K; k++) s += v[k] * W[k * N + j];
    out[j] = s;
}

__global__ void k_cast(const float* __restrict__ in, __nv_bfloat16* __restrict__ out, int n) {
    int i = blockIdx.x * blockDim.x + threadIdx.x;
    if (i < n) out[i] = __float2bfloat16_rn(in[i]);
}

__global__ void k_fold_w1(const float* __restrict__ dw, const float* __restrict__ W1,
                          __nv_bfloat16* __restrict__ out) {
    int i = blockIdx.x * blockDim.x + threadIdx.x;
    if (i < CH_ * CH_) out[i] = __float2bfloat16_rn(dw[i / CH_] * W1[i]);
}

// ---------------- LayerNorm -> bf16 ----------------------------------------
__global__ void ln_kernel(const float* __restrict__ x, const float* __restrict__ gamma,
                          const float* __restrict__ beta, __nv_bfloat16* __restrict__ z) {
    __shared__ float sh[16];
    int row = blockIdx.x;
    int tid = threadIdx.x;
    float4 v = ((const float4*)(x + (size_t)row * C_))[tid];
    float s  = v.x + v.y + v.z + v.w;
    float ss = v.x * v.x + v.y * v.y + v.z * v.z + v.w * v.w;
#pragma unroll
    for (int o = 16; o; o >>= 1) {
        s  += __shfl_xor_sync(0xFFFFFFFFu, s, o);
        ss += __shfl_xor_sync(0xFFFFFFFFu, ss, o);
    }
    int warp = tid >> 5;
    if ((tid & 31) == 0) { sh[warp] = s; sh[warp + 8] = ss; }
    __syncthreads();
    if (tid < 32) {
        float s2  = (tid < 8) ? sh[tid] : 0.f;
        float ss2 = (tid < 8) ? sh[tid + 8] : 0.f;
#pragma unroll
        for (int o = 4; o; o >>= 1) {
            s2  += __shfl_xor_sync(0xFFFFFFFFu, s2, o);
            ss2 += __shfl_xor_sync(0xFFFFFFFFu, ss2, o);
        }
        if (tid == 0) { sh[0] = s2; sh[1] = ss2; }
    }
    __syncthreads();
    float mean = sh[0] * (1.f / C_);
    float var  = sh[1] * (1.f / C_) - mean * mean;
    float rstd = rsqrtf(var + 1e-5f);
    float4 gm = ((const float4*)gamma)[tid];
    float4 bt = ((const float4*)beta)[tid];
    union { __nv_bfloat16 h[4]; uint2 u; } pk;
    pk.h[0] = __float2bfloat16_rn((v.x - mean) * rstd * gm.x + bt.x);
    pk.h[1] = __float2bfloat16_rn((v.y - mean) * rstd * gm.y + bt.y);
    pk.h[2] = __float2bfloat16_rn((v.z - mean) * rstd * gm.z + bt.z);
    pk.h[3] = __float2bfloat16_rn((v.w - mean) * rstd * gm.w + bt.w);
    ((uint2*)(z + (size_t)row * C_))[tid] = pk.u;
}

// ---------------- main bf16 tensor-core GEMM --------------------------------
// C[M,N] = A[M,K](bf16 rm) @ W[K,N](bf16 rm), fp32 accum, fused epilogues.
// EPI: 0 raw f32 store | 1 GLU (reads aux=sa, bias=bg, bias2=bd) -> bf16
//      2 bias+gelu(tanh) -> bf16 | 3 bias -> bf16 | 4 bias + residual mix (aux=x) -> f32

#define BM 128
#define BN 128
#define BKK 32
#define SSTR 48   // BKK + 16 pad (bf16 elems); row stride 96B

__device__ __forceinline__ void mma16816(float* c, const uint32_t* a, const uint32_t* b) {
    asm volatile(
        "mma.sync.aligned.m16n8k16.row.col.f32.bf16.bf16.f32 "
        "{%0,%1,%2,%3}, {%4,%5,%6,%7}, {%8,%9}, {%0,%1,%2,%3};\n"
        : "+f"(c[0]), "+f"(c[1]), "+f"(c[2]), "+f"(c[3])
        : "r"(a[0]), "r"(a[1]), "r"(a[2]), "r"(a[3]), "r"(b[0]), "r"(b[1]));
}

__device__ __forceinline__ float gelu_tanh(float t) {
    float t3 = t * t * t;
    return 0.5f * t * (1.0f + tanhf(0.7978845608028654f * (t + 0.044715f * t3)));
}

template <int EPI>
__global__ __launch_bounds__(256)
void gemm_bf16(const __nv_bfloat16* __restrict__ A, const __nv_bfloat16* __restrict__ W,
               int M, int N, int K,
               const float* __restrict__ bias, const float* __restrict__ bias2,
               const float* __restrict__ aux, void* __restrict__ Cout) {
    __shared__ __nv_bfloat16 As[BM][SSTR];
    __shared__ __nv_bfloat16 Bt[BN][SSTR];

    int tid = threadIdx.x;
    int warp = tid >> 5, lane = tid & 31;
    int warpM = warp & 1;      // 2 warps along M (64 rows each)
    int warpN = warp >> 1;     // 4 warps along N (32 cols each)
    int g = lane >> 2, tig = lane & 3;
    int bm = blockIdx.y * BM;
    int bn = blockIdx.x * BN;

    float acc[4][4][4];
#pragma unroll
    for (int a0 = 0; a0 < 4; a0++)
#pragma unroll
        for (int a1 = 0; a1 < 4; a1++)
#pragma unroll
            for (int a2 = 0; a2 < 4; a2++) acc[a0][a1][a2] = 0.f;

    int arow = tid >> 2;            // 0..63
    int acol = (tid & 3) * 8;       // 0,8,16,24
    int brow = tid >> 4;            // 0..15 (k)
    int bcol = (tid & 15) * 8;      // n 0..120

    for (int k0 = 0; k0 < K; k0 += BKK) {
        *(uint4*)&As[arow][acol]      = *(const uint4*)&A[(size_t)(bm + arow) * K + k0 + acol];
        *(uint4*)&As[arow + 64][acol] = *(const uint4*)&A[(size_t)(bm + arow + 64) * K + k0 + acol];
        {
            uint4 v0 = *(const uint4*)&W[(size_t)(k0 + brow) * N + bn + bcol];
            uint4 v1 = *(const uint4*)&W[(size_t)(k0 + brow + 16) * N + bn + bcol];
            const __nv_bfloat16* p0 = (const __nv_bfloat16*)&v0;
            const __nv_bfloat16* p1 = (const __nv_bfloat16*)&v1;
#pragma unroll
            for (int j = 0; j < 8; j++) {
                Bt[bcol + j][brow]      = p0[j];
                Bt[bcol + j][brow + 16] = p1[j];
            }
        }
        __syncthreads();
#pragma unroll
        for (int ks = 0; ks < 2; ks++) {
            int kk = ks * 16;
            uint32_t aF[4][4];
#pragma unroll
            for (int mt = 0; mt < 4; mt++) {
                int r = warpM * 64 + mt * 16;
                aF[mt][0] = *(const uint32_t*)&As[r + g][kk + 2 * tig];
                aF[mt][1] = *(const uint32_t*)&As[r + 8 + g][kk + 2 * tig];
                aF[mt][2] = *(const uint32_t*)&As[r + g][kk + 8 + 2 * tig];
                aF[mt][3] = *(const uint32_t*)&As[r + 8 + g][kk + 8 + 2 * tig];
            }
            uint32_t bF[4][2];
#pragma unroll
            for (int nt = 0; nt < 4; nt++) {
                int c = warpN * 32 + nt * 8;
                bF[nt][0] = *(const uint32_t*)&Bt[c + g][kk + 2 * tig];
                bF[nt][1] = *(const uint32_t*)&Bt[c + g][kk + 8 + 2 * tig];
            }
#pragma unroll
            for (int mt = 0; mt < 4; mt++)
#pragma unroll
                for (int nt = 0; nt < 4; nt++) mma16816(acc[mt][nt], aF[mt], bF[nt]);
        }
        __syncthreads();
    }

    // epilogue
#pragma unroll
    for (int mt = 0; mt < 4; mt++) {
#pragma unroll
        for (int nt = 0; nt < 4; nt++) {
#pragma unroll
            for (int i = 0; i < 4; i++) {
                int row = bm + warpM * 64 + mt * 16 + g + ((i >= 2) ? 8 : 0);
                int col = bn + warpN * 32 + nt * 8 + tig * 2 + (i & 1);
                float v = acc[mt][nt][i];
                size_t oidx = (size_t)row * N + col;
                if (EPI == 0) {
                    ((float*)Cout)[oidx] = v;
                } else if (EPI == 1) {
                    float a = aux[oidx] + bias2[col];
                    float sgm = 1.0f / (1.0f + expf(-(v + bias[col])));
                    ((__nv_bfloat16*)Cout)[oidx] = __float2bfloat16_rn(a * sgm);
                } else if (EPI == 2) {
                    ((__nv_bfloat16*)Cout)[oidx] = __float2bfloat16_rn(gelu_tanh(v + bias[col]));
                } else if (EPI == 3) {
                    ((__nv_bfloat16*)Cout)[oidx] = __float2bfloat16_rn(v + bias[col]);
                } else {  // 4: residual mix
                    ((float*)Cout)[oidx] = 0.5f * (v + bias[col]) + 0.5f * aux[oidx];
                }
            }
        }
    }
}

// ---------------- launch ----------------------------------------------------
static void* sym(const void* s) {
    void* p = nullptr;
    cudaGetSymbolAddress(&p, s);
    return p;
}

extern "C" void kernel_launch(void* const* d_in, const int* in_sizes, int n_in,
                              void* d_out, int out_size) {
    const float* x    = (const float*)d_in[0];
    const float* ln_g = (const float*)d_in[1];
    const float* ln_b = (const float*)d_in[2];
    const float* Wd   = (const float*)d_in[3];
    const float* bd   = (const float*)d_in[4];
    const float* Wg   = (const float*)d_in[5];
    const float* bg   = (const float*)d_in[6];
    const float* dw_w = (const float*)d_in[7];
    const float* dw_b = (const float*)d_in[8];
    const float* W1   = (const float*)d_in[9];
    const float* b1   = (const float*)d_in[10];
    const float* W2   = (const float*)d_in[11];
    const float* b2   = (const float*)d_in[12];
    // d_in[13..16] = Wq,bq,Wk,bk : dead (softmax over 1 key == 1)
    const float* Wv   = (const float*)d_in[17];
    const float* bv   = (const float*)d_in[18];
    const float* Wo   = (const float*)d_in[19];
    const float* bo   = (const float*)d_in[20];
    const float* Wu   = (const float*)d_in[21];
    const float* bu   = (const float*)d_in[22];
    const float* Wld  = (const float*)d_in[23];
    const float* Wlu  = (const float*)d_in[24];
    float* out = (float*)d_out;

    float* fWvo = (float*)sym(g_fWvo);
    float* fW23 = (float*)sym(g_fW23);
    float* fT1  = (float*)sym(g_fT1);
    float* fWuE = (float*)sym(g_fWuE);
    float* b1p  = (float*)sym(g_b1p);
    float* bvo  = (float*)sym(g_bvo);
    float* b23  = (float*)sym(g_b23);
    float* t16  = (float*)sym(g_t16);
    float* buE  = (float*)sym(g_buE);
    __nv_bfloat16* zW  = (__nv_bfloat16*)sym(g_z);
    float*         saW = (float*)sym(g_sa);
    __nv_bfloat16* uW  = (__nv_bfloat16*)sym(g_u);
    __nv_bfloat16* pW  = (__nv_bfloat16*)sym(g_p);
    __nv_bfloat16* qW  = (__nv_bfloat16*)sym(g_q);
    __nv_bfloat16* bWd  = (__nv_bfloat16*)sym(g_Wd);
    __nv_bfloat16* bWg  = (__nv_bfloat16*)sym(g_Wg);
    __nv_bfloat16* bW1  = (__nv_bfloat16*)sym(g_W1);
    __nv_bfloat16* bW23 = (__nv_bfloat16*)sym(g_W23);
    __nv_bfloat16* bWuE = (__nv_bfloat16*)sym(g_WuE);

    // ---- prep: fold the whole tail of the network into 5 matrices ----
    k_gemm_naive<<<(CH_ * CH_ + 255) / 256, 256>>>(Wv, Wo, nullptr, fWvo, CH_, CH_, CH_);
    k_gemm_naive<<<(CH_ * CH_ + 255) / 256, 256>>>(W2, fWvo, nullptr, fW23, CH_, CH_, CH_);
    k_gemm_naive<<<(CH_ * RANK_ + 255) / 256, 256>>>(Wu, Wld, nullptr, fT1, CH_, RANK_, C_);
    k_gemm_naive<<<(CH_ * C_ + 255) / 256, 256>>>(fT1, Wlu, Wu, fWuE, CH_, C_, RANK_);
    k_vecmat<<<1, CH_>>>(dw_b, W1, b1, b1p, CH_, CH_);
    k_vecmat<<<1, CH_>>>(bv, Wo, bo, bvo, CH_, CH_);
    k_vecmat<<<1, CH_>>>(b2, fWvo, bvo, b23, CH_, CH_);
    k_vecmat<<<1, RANK_>>>(bu, Wld, nullptr, t16, C_, RANK_);
    k_vecmat<<<4, 256>>>(t16, Wlu, bu, buE, RANK_, C_);
    k_cast<<<(C_ * CH_ + 255) / 256, 256>>>(Wd, bWd, C_ * CH_);
    k_cast<<<(C_ * CH_ + 255) / 256, 256>>>(Wg, bWg, C_ * CH_);
    k_cast<<<(CH_ * CH_ + 255) / 256, 256>>>(fW23, bW23, CH_ * CH_);
    k_cast<<<(CH_ * C_ + 255) / 256, 256>>>(fWuE, bWuE, CH_ * C_);
    k_fold_w1<<<(CH_ * CH_ + 255) / 256, 256>>>(dw_w, W1, bW1);

    // ---- main pipeline ----
    ln_kernel<<<B_, 256>>>(x, ln_g, ln_b, zW);

    dim3 gK1024(CH_ / BN, B_ / BM);                       // (2, 256)
    gemm_bf16<0><<<gK1024, 256>>>(zW, bWd, B_, CH_, C_, nullptr, nullptr, nullptr, saW);
    gemm_bf16<1><<<gK1024, 256>>>(zW, bWg, B_, CH_, C_, bg, bd, saW, uW);

    dim3 gK256(CH_ / BN, B_ / BM);                        // (2, 256)
    gemm_bf16<2><<<gK256, 256>>>(uW, bW1, B_, CH_, CH_, b1p, nullptr, nullptr, pW);
    gemm_bf16<3><<<gK256, 256>>>(pW, bW23, B_, CH_, CH_, b23, nullptr, nullptr, qW);

    dim3 gUp(C_ / BN, B_ / BM);                           // (8, 256)
    gemm_bf16<4><<<gUp, 256>>>(qW, bWuE, B_, C_, CH_, buE, nullptr, x, out);
}

// round 3
// speedup vs baseline: 2.2813x; 2.2813x over previous
#include <cuda_runtime.h>
#include <cuda_bf16.h>
#include <math.h>
#include <stdint.h>

#define B_  32768
#define C_  1024
#define CH_ 256
#define RANK_ 16

// ---------------- scratch (device globals; no allocation allowed) ----------
__device__ __nv_bfloat16 g_z [B_ * C_];    // LN output, bf16
__device__ float         g_sa[B_ * CH_];   // raw z@Wd
__device__ __nv_bfloat16 g_u [B_ * CH_];   // GLU output
__device__ __nv_bfloat16 g_p [B_ * CH_];   // gelu(u@W1'+b1')
__device__ __nv_bfloat16 g_q [B_ * CH_];   // p@W23+b23

__device__ __nv_bfloat16 g_Wd [C_ * CH_];
__device__ __nv_bfloat16 g_Wg [C_ * CH_];
__device__ __nv_bfloat16 g_W1 [CH_ * CH_];   // dw-folded
__device__ __nv_bfloat16 g_W23[CH_ * CH_];   // W2@Wv@Wo
__device__ __nv_bfloat16 g_WuE[CH_ * C_];    // Wu(I + Wld Wlu)

__device__ float g_fWvo[CH_ * CH_];
__device__ float g_fW23[CH_ * CH_];
__device__ float g_fT1 [CH_ * RANK_];
__device__ float g_fWuE[CH_ * C_];
__device__ float g_b1p[CH_], g_bvo[CH_], g_b23[CH_], g_t16[RANK_], g_buE[C_];

// ---------------- tiny prep kernels ----------------------------------------
__global__ void k_gemm_naive(const float* __restrict__ A, const float* __restrict__ Bm,
                             const float* __restrict__ addC, float* __restrict__ Cm,
                             int M, int N, int K) {
    int idx = blockIdx.x * blockDim.x + threadIdx.x;
    if (idx >= M * N) return;
    int i = idx / N, j = idx % N;
    float s = addC ? addC[idx] : 0.f;
    for (int k = 0; k < K; k++) s += A[i * K + k] * Bm[k * N + j];
    Cm[idx] = s;
}

__global__ void k_vecmat(const float* __restrict__ v, const float* __restrict__ W,
                         const float* __restrict__ add, float* __restrict__ out,
                         int K, int N) {
    int j = blockIdx.x * blockDim.x + threadIdx.x;
    if (j >= N) return;
    float s = add ? add[j] : 0.f;
    for (int k = 0; k < K; k++) s += v[k] * W[k * N + j];
    out[j] = s;
}

__global__ void k_cast(const float* __restrict__ in, __nv_bfloat16* __restrict__ out, int n) {
    int i = blockIdx.x * blockDim.x + threadIdx.x;
    if (i < n) out[i] = __float2bfloat16_rn(in[i]);
}

__global__ void k_fold_w1(const float* __restrict__ dw, const float* __restrict__ W1,
                          __nv_bfloat16* __restrict__ out) {
    int i = blockIdx.x * blockDim.x + threadIdx.x;
    if (i < CH_ * CH_) out[i] = __float2bfloat16_rn(dw[i / CH_] * W1[i]);
}

// ---------------- LayerNorm -> bf16 ----------------------------------------
__global__ void ln_kernel(const float* __restrict__ x, const float* __restrict__ gamma,
                          const float* __restrict__ beta, __nv_bfloat16* __restrict__ z) {
    __shared__ float sh[16];
    int row = blockIdx.x;
    int tid = threadIdx.x;
    float4 v = ((const float4*)(x + (size_t)row * C_))[tid];
    float s  = v.x + v.y + v.z + v.w;
    float ss = v.x * v.x + v.y * v.y + v.z * v.z + v.w * v.w;
#pragma unroll
    for (int o = 16; o; o >>= 1) {
        s  += __shfl_xor_sync(0xFFFFFFFFu, s, o);
        ss += __shfl_xor_sync(0xFFFFFFFFu, ss, o);
    }
    int warp = tid >> 5;
    if ((tid & 31) == 0) { sh[warp] = s; sh[warp + 8] = ss; }
    __syncthreads();
    if (tid < 32) {
        float s2  = (tid < 8) ? sh[tid] : 0.f;
        float ss2 = (tid < 8) ? sh[tid + 8] : 0.f;
#pragma unroll
        for (int o = 4; o; o >>= 1) {
            s2  += __shfl_xor_sync(0xFFFFFFFFu, s2, o);
            ss2 += __shfl_xor_sync(0xFFFFFFFFu, ss2, o);
        }
        if (tid == 0) { sh[0] = s2; sh[1] = ss2; }
    }
    __syncthreads();
    float mean = sh[0] * (1.f / C_);
    float var  = sh[1] * (1.f / C_) - mean * mean;
    float rstd = rsqrtf(var + 1e-5f);
    float4 gm = ((const float4*)gamma)[tid];
    float4 bt = ((const float4*)beta)[tid];
    union { __nv_bfloat16 h[4]; uint2 u; } pk;
    pk.h[0] = __float2bfloat16_rn((v.x - mean) * rstd * gm.x + bt.x);
    pk.h[1] = __float2bfloat16_rn((v.y - mean) * rstd * gm.y + bt.y);
    pk.h[2] = __float2bfloat16_rn((v.z - mean) * rstd * gm.z + bt.z);
    pk.h[3] = __float2bfloat16_rn((v.w - mean) * rstd * gm.w + bt.w);
    ((uint2*)(z + (size_t)row * C_))[tid] = pk.u;
}

// ---------------- async-copy + ldmatrix bf16 GEMM ---------------------------
// C[M,N] = A[M,K](bf16 rm) @ W[K,N](bf16 rm), fp32 accum, fused epilogues.
// BM=128, BN=128, BK=32, 3-stage cp.async pipeline, XOR-swizzled smem,
// ldmatrix fragment loads (trans for B), 8 warps (2 x 4), warp tile 64x32.
// EPI: 0 raw f32 | 1 GLU (aux=sa raw-d, bias=bg, bias2=bd) -> bf16
//      2 bias+gelu -> bf16 | 3 bias -> bf16 | 4 bias + 0.5/0.5 residual (aux=x) -> f32

__device__ __forceinline__ uint32_t smem_u32(const void* p) {
    return (uint32_t)__cvta_generic_to_shared(p);
}
__device__ __forceinline__ void cp16(uint32_t d, const void* s) {
    asm volatile("cp.async.cg.shared.global [%0], [%1], 16;\n" :: "r"(d), "l"(s));
}
__device__ __forceinline__ void cp_commit() {
    asm volatile("cp.async.commit_group;\n");
}
__device__ __forceinline__ void cp_wait2() {
    asm volatile("cp.async.wait_group 2;\n");
}
__device__ __forceinline__ void ldsm_x4(uint32_t* r, uint32_t a) {
    asm volatile("ldmatrix.sync.aligned.m8n8.x4.shared.b16 {%0,%1,%2,%3}, [%4];\n"
                 : "=r"(r[0]), "=r"(r[1]), "=r"(r[2]), "=r"(r[3]) : "r"(a));
}
__device__ __forceinline__ void ldsm_x4_t(uint32_t* r, uint32_t a) {
    asm volatile("ldmatrix.sync.aligned.m8n8.x4.trans.shared.b16 {%0,%1,%2,%3}, [%4];\n"
                 : "=r"(r[0]), "=r"(r[1]), "=r"(r[2]), "=r"(r[3]) : "r"(a));
}
__device__ __forceinline__ void mma16816(float* c, const uint32_t* a, const uint32_t* b) {
    asm volatile(
        "mma.sync.aligned.m16n8k16.row.col.f32.bf16.bf16.f32 "
        "{%0,%1,%2,%3}, {%4,%5,%6,%7}, {%8,%9}, {%0,%1,%2,%3};\n"
        : "+f"(c[0]), "+f"(c[1]), "+f"(c[2]), "+f"(c[3])
        : "r"(a[0]), "r"(a[1]), "r"(a[2]), "r"(a[3]), "r"(b[0]), "r"(b[1]));
}
__device__ __forceinline__ float gelu_tanh(float t) {
    float t3 = t * t * t;
    return 0.5f * t * (1.0f + tanhf(0.7978845608028654f * (t + 0.044715f * t3)));
}

#define ASTAGE 8192  // bytes per A stage (128 x 32 bf16)
#define BSTAGE 8192  // bytes per B stage (32 x 128 bf16)

template <int EPI>
__global__ __launch_bounds__(256, 2)
void gemm_bf16(const __nv_bfloat16* __restrict__ A, const __nv_bfloat16* __restrict__ W,
               int M, int N, int K,
               const float* __restrict__ bias, const float* __restrict__ bias2,
               const float* __restrict__ aux, void* __restrict__ Cout) {
    __shared__ __nv_bfloat16 As[3 * 4096];
    __shared__ __nv_bfloat16 Bs[3 * 4096];

    const int tid  = threadIdx.x;
    const int warp = tid >> 5, lane = tid & 31;
    const int warpM = warp & 1;      // 2 warps along M (64 rows each)
    const int warpN = warp >> 1;     // 4 warps along N (32 cols each)
    const int bm = blockIdx.y * 128;
    const int bn = blockIdx.x * 128;

    // ---- cp.async store addresses (XOR swizzle) ----
    const int r  = tid >> 2;           // A row 0..63 (and +64)
    const int c  = tid & 3;            // A 16B chunk 0..3
    const int kb = tid >> 4;           // B k-row 0..15 (and +16)
    const int cb = tid & 15;           // B 16B chunk 0..15
    const uint32_t sAb = smem_u32(As);
    const uint32_t sBb = smem_u32(Bs);
    const uint32_t aSt0 = sAb + (uint32_t)(r * 32 + ((c ^ ((r >> 1) & 3)) << 3)) * 2;
    const uint32_t aSt1 = sAb + (uint32_t)((r + 64) * 32 + ((c ^ ((r >> 1) & 3)) << 3)) * 2;
    const uint32_t bSt0 = sBb + (uint32_t)(kb * 128 + ((cb ^ (kb & 7)) << 3)) * 2;
    const uint32_t bSt1 = sBb + (uint32_t)((kb + 16) * 128 + ((cb ^ (kb & 7)) << 3)) * 2;

    const __nv_bfloat16* pa = A + (size_t)(bm + r) * K + c * 8;
    const __nv_bfloat16* pb = W + (size_t)kb * N + bn + cb * 8;
    const size_t paRow64 = (size_t)64 * K;
    const size_t pbRow16 = (size_t)16 * N;
    const size_t pbStep  = (size_t)32 * N;

    float acc[4][4][4];
#pragma unroll
    for (int a0 = 0; a0 < 4; a0++)
#pragma unroll
        for (int a1 = 0; a1 < 4; a1++)
#pragma unroll
            for (int a2 = 0; a2 < 4; a2++) acc[a0][a1][a2] = 0.f;

    // ---- ldmatrix address components ----
    const int l15 = lane & 15, hi = lane >> 4, l7 = lane & 7;
    int rowA[4], swzA[4];
#pragma unroll
    for (int mt = 0; mt < 4; mt++) {
        rowA[mt] = warpM * 64 + mt * 16 + l15;
        swzA[mt] = (rowA[mt] >> 1) & 3;
    }

    const int KT = K >> 5;  // K / 32

    // prologue: stages 0,1 <- tiles 0,1
    cp16(aSt0, pa); cp16(aSt1, pa + paRow64);
    cp16(bSt0, pb); cp16(bSt1, pb + pbRow16);
    cp_commit();
    pa += 32; pb += pbStep;
    cp16(aSt0 + ASTAGE, pa); cp16(aSt1 + ASTAGE, pa + paRow64);
    cp16(bSt0 + BSTAGE, pb); cp16(bSt1 + BSTAGE, pb + pbRow16);
    cp_commit();
    pa += 32; pb += pbStep;

    int sL = 2, sC = 0;
    for (int kt = 0; kt < KT; kt++) {
        if (kt + 2 < KT) {
            uint32_t ao = (uint32_t)sL * ASTAGE, bo = (uint32_t)sL * BSTAGE;
            cp16(aSt0 + ao, pa); cp16(aSt1 + ao, pa + paRow64);
            cp16(bSt0 + bo, pb); cp16(bSt1 + bo, pb + pbRow16);
            pa += 32; pb += pbStep;
        }
        cp_commit();
        cp_wait2();
        __syncthreads();

        const uint32_t sA = sAb + (uint32_t)sC * ASTAGE;
        const uint32_t sB = sBb + (uint32_t)sC * BSTAGE;
#pragma unroll
        for (int ks = 0; ks < 2; ks++) {
            uint32_t aF[4][4];
#pragma unroll
            for (int mt = 0; mt < 4; mt++) {
                uint32_t addr = sA + (uint32_t)(rowA[mt] * 32 +
                                  (((ks * 2 + hi) ^ swzA[mt]) << 3)) * 2;
                ldsm_x4(aF[mt], addr);
            }
            uint32_t bF[8];
#pragma unroll
            for (int half = 0; half < 2; half++) {
                int c0 = warpN * 4 + half * 2;
                uint32_t addr = sB + (uint32_t)((ks * 16 + l15) * 128 +
                                  (((c0 + hi) ^ l7) << 3)) * 2;
                ldsm_x4_t(&bF[half * 4], addr);
            }
#pragma unroll
            for (int mt = 0; mt < 4; mt++)
#pragma unroll
                for (int nt = 0; nt < 4; nt++)
                    mma16816(acc[mt][nt], aF[mt], &bF[nt * 2]);
        }
        __syncthreads();
        sL = (sL == 2) ? 0 : sL + 1;
        sC = (sC == 2) ? 0 : sC + 1;
    }

    // ---- epilogue (vectorized pair stores) ----
    const int g = lane >> 2, tig = lane & 3;
#pragma unroll
    for (int mt = 0; mt < 4; mt++) {
#pragma unroll
        for (int nt = 0; nt < 4; nt++) {
            int col = bn + warpN * 32 + nt * 8 + tig * 2;
#pragma unroll
            for (int h = 0; h < 2; h++) {
                int row = bm + warpM * 64 + mt * 16 + g + h * 8;
                float v0 = acc[mt][nt][2 * h], v1 = acc[mt][nt][2 * h + 1];
                size_t oi = (size_t)row * N + col;
                if (EPI == 0) {
                    *reinterpret_cast<float2*>((float*)Cout + oi) = make_float2(v0, v1);
                } else if (EPI == 1) {
                    float2 a2 = *reinterpret_cast<const float2*>(aux + oi);
                    float s0 = 1.0f / (1.0f + expf(-(v0 + bias[col])));
                    float s1 = 1.0f / (1.0f + expf(-(v1 + bias[col + 1])));
                    __nv_bfloat162 o;
                    o.x = __float2bfloat16_rn((a2.x + bias2[col]) * s0);
                    o.y = __float2bfloat16_rn((a2.y + bias2[col + 1]) * s1);
                    *reinterpret_cast<__nv_bfloat162*>((__nv_bfloat16*)Cout + oi) = o;
                } else if (EPI == 2) {
                    __nv_bfloat162 o;
                    o.x = __float2bfloat16_rn(gelu_tanh(v0 + bias[col]));
                    o.y = __float2bfloat16_rn(gelu_tanh(v1 + bias[col + 1]));
                    *reinterpret_cast<__nv_bfloat162*>((__nv_bfloat16*)Cout + oi) = o;
                } else if (EPI == 3) {
                    __nv_bfloat162 o;
                    o.x = __float2bfloat16_rn(v0 + bias[col]);
                    o.y = __float2bfloat16_rn(v1 + bias[col + 1]);
                    *reinterpret_cast<__nv_bfloat162*>((__nv_bfloat16*)Cout + oi) = o;
                } else {  // 4: residual mix, fp32 out
                    float2 a2 = *reinterpret_cast<const float2*>(aux + oi);
                    float2 o = make_float2(0.5f * (v0 + bias[col]) + 0.5f * a2.x,
                                           0.5f * (v1 + bias[col + 1]) + 0.5f * a2.y);
                    *reinterpret_cast<float2*>((float*)Cout + oi) = o;
                }
            }
        }
    }
}

// ---------------- launch ----------------------------------------------------
static void* sym(const void* s) {
    void* p = nullptr;
    cudaGetSymbolAddress(&p, s);
    return p;
}

extern "C" void kernel_launch(void* const* d_in, const int* in_sizes, int n_in,
                              void* d_out, int out_size) {
    const float* x    = (const float*)d_in[0];
    const float* ln_g = (const float*)d_in[1];
    const float* ln_b = (const float*)d_in[2];
    const float* Wd   = (const float*)d_in[3];
    const float* bd   = (const float*)d_in[4];
    const float* Wg   = (const float*)d_in[5];
    const float* bg   = (const float*)d_in[6];
    const float* dw_w = (const float*)d_in[7];
    const float* dw_b = (const float*)d_in[8];
    const float* W1   = (const float*)d_in[9];
    const float* b1   = (const float*)d_in[10];
    const float* W2   = (const float*)d_in[11];
    const float* b2   = (const float*)d_in[12];
    // d_in[13..16] = Wq,bq,Wk,bk : dead (softmax over 1 key == 1)
    const float* Wv   = (const float*)d_in[17];
    const float* bv   = (const float*)d_in[18];
    const float* Wo   = (const float*)d_in[19];
    const float* bo   = (const float*)d_in[20];
    const float* Wu   = (const float*)d_in[21];
    const float* bu   = (const float*)d_in[22];
    const float* Wld  = (const float*)d_in[23];
    const float* Wlu  = (const float*)d_in[24];
    float* out = (float*)d_out;

    float* fWvo = (float*)sym(g_fWvo);
    float* fW23 = (float*)sym(g_fW23);
    float* fT1  = (float*)sym(g_fT1);
    float* fWuE = (float*)sym(g_fWuE);
    float* b1p  = (float*)sym(g_b1p);
    float* bvo  = (float*)sym(g_bvo);
    float* b23  = (float*)sym(g_b23);
    float* t16  = (float*)sym(g_t16);
    float* buE  = (float*)sym(g_buE);
    __nv_bfloat16* zW  = (__nv_bfloat16*)sym(g_z);
    float*         saW = (float*)sym(g_sa);
    __nv_bfloat16* uW  = (__nv_bfloat16*)sym(g_u);
    __nv_bfloat16* pW  = (__nv_bfloat16*)sym(g_p);
    __nv_bfloat16* qW  = (__nv_bfloat16*)sym(g_q);
    __nv_bfloat16* bWd  = (__nv_bfloat16*)sym(g_Wd);
    __nv_bfloat16* bWg  = (__nv_bfloat16*)sym(g_Wg);
    __nv_bfloat16* bW1  = (__nv_bfloat16*)sym(g_W1);
    __nv_bfloat16* bW23 = (__nv_bfloat16*)sym(g_W23);
    __nv_bfloat16* bWuE = (__nv_bfloat16*)sym(g_WuE);

    // ---- prep: fold the whole tail of the network into 5 matrices ----
    k_gemm_naive<<<(CH_ * CH_ + 255) / 256, 256>>>(Wv, Wo, nullptr, fWvo, CH_, CH_, CH_);
    k_gemm_naive<<<(CH_ * CH_ + 255) / 256, 256>>>(W2, fWvo, nullptr, fW23, CH_, CH_, CH_);
    k_gemm_naive<<<(CH_ * RANK_ + 255) / 256, 256>>>(Wu, Wld, nullptr, fT1, CH_, RANK_, C_);
    k_gemm_naive<<<(CH_ * C_ + 255) / 256, 256>>>(fT1, Wlu, Wu, fWuE, CH_, C_, RANK_);
    k_vecmat<<<1, CH_>>>(dw_b, W1, b1, b1p, CH_, CH_);
    k_vecmat<<<1, CH_>>>(bv, Wo, bo, bvo, CH_, CH_);
    k_vecmat<<<1, CH_>>>(b2, fWvo, bvo, b23, CH_, CH_);
    k_vecmat<<<1, RANK_>>>(bu, Wld, nullptr, t16, C_, RANK_);
    k_vecmat<<<4, 256>>>(t16, Wlu, bu, buE, RANK_, C_);
    k_cast<<<(C_ * CH_ + 255) / 256, 256>>>(Wd, bWd, C_ * CH_);
    k_cast<<<(C_ * CH_ + 255) / 256, 256>>>(Wg, bWg, C_ * CH_);
    k_cast<<<(CH_ * CH_ + 255) / 256, 256>>>(fW23, bW23, CH_ * CH_);
    k_cast<<<(CH_ * C_ + 255) / 256, 256>>>(fWuE, bWuE, CH_ * C_);
    k_fold_w1<<<(CH_ * CH_ + 255) / 256, 256>>>(dw_w, W1, bW1);

    // ---- main pipeline ----
    ln_kernel<<<B_, 256>>>(x, ln_g, ln_b, zW);

    dim3 gK(CH_ / 128, B_ / 128);                          // (2, 256)
    gemm_bf16<0><<<gK, 256>>>(zW, bWd, B_, CH_, C_, nullptr, nullptr, nullptr, saW);
    gemm_bf16<1><<<gK, 256>>>(zW, bWg, B_, CH_, C_, bg, bd, saW, uW);
    gemm_bf16<2><<<gK, 256>>>(uW, bW1, B_, CH_, CH_, b1p, nullptr, nullptr, pW);
    gemm_bf16<3><<<gK, 256>>>(pW, bW23, B_, CH_, CH_, b23, nullptr, nullptr, qW);

    dim3 gUp(C_ / 128, B_ / 128);                          // (8, 256)
    gemm_bf16<4><<<gUp, 256>>>(qW, bWuE, B_, C_, CH_, buE, nullptr, x, out);
}

// round 5
// speedup vs baseline: 3.1277x; 1.3710x over previous
#include <cuda_runtime.h>
#include <cuda_bf16.h>
#include <math.h>
#include <stdint.h>

#define B_  32768
#define C_  1024
#define CH_ 256
#define RANK_ 16

// ---------------- scratch (device globals; no allocation allowed) ------------
__device__ __nv_bfloat16 g_z [B_ * C_];     // LN output
__device__ __nv_bfloat16 g_u [B_ * CH_];    // GLU output
__device__ __nv_bfloat16 g_p [B_ * CH_];    // gelu output

__device__ __nv_bfloat16 g_Wglu[C_ * 512];  // [K=1024][512] interleaved 8d|8g per 16
__device__ __nv_bfloat16 g_W1b [CH_ * CH_]; // [K=256][N=256] dw-folded W1
__device__ __nv_bfloat16 g_Wtb [CH_ * C_];  // [K=256][N=1024] Wtail

__device__ float g_fWvo[CH_ * CH_];
__device__ float g_fW23[CH_ * CH_];
__device__ float g_fT1 [CH_ * RANK_];
__device__ float g_fWuE[CH_ * C_];
__device__ float g_fWt [CH_ * C_];
__device__ float g_b1p[CH_], g_bvo[CH_], g_t16[RANK_], g_b23[CH_], g_buE[C_], g_bt[C_];

// ---------------- consolidated prep kernels ----------------------------------
// P0: fWvo, fT1, b1p, bvo, t16, W1b, Wglu
#define P0_FWVO   0
#define P0_FT1    65536
#define P0_B1P    69632
#define P0_BVO    69888
#define P0_T16    70144
#define P0_W1B    70160
#define P0_WGLU   135696
#define P0_TOTAL  659984

__global__ void prep0(const float* __restrict__ Wv, const float* __restrict__ Wo,
                      const float* __restrict__ bo, const float* __restrict__ Wu,
                      const float* __restrict__ Wld, const float* __restrict__ dw_w,
                      const float* __restrict__ dw_b, const float* __restrict__ W1,
                      const float* __restrict__ b1, const float* __restrict__ bv,
                      const float* __restrict__ bu, const float* __restrict__ Wd,
                      const float* __restrict__ Wg) {
    int i = blockIdx.x * blockDim.x + threadIdx.x;
    if (i < P0_FT1) {                      // fWvo = Wv @ Wo
        int r = i >> 8, c = i & 255;
        float s = 0.f;
#pragma unroll 8
        for (int k = 0; k < CH_; k++) s += Wv[r * CH_ + k] * Wo[k * CH_ + c];
        g_fWvo[i] = s;
    } else if (i < P0_B1P) {               // fT1 = Wu @ Wld
        int j = i - P0_FT1;
        int r = j >> 4, c = j & 15;
        float s = 0.f;
#pragma unroll 8
        for (int k = 0; k < C_; k++) s += Wu[r * C_ + k] * Wld[k * RANK_ + c];
        g_fT1[j] = s;
    } else if (i < P0_BVO) {               // b1p = dw_b @ W1 + b1
        int j = i - P0_B1P;
        float s = b1[j];
#pragma unroll 8
        for (int k = 0; k < CH_; k++) s += dw_b[k] * W1[k * CH_ + j];
        g_b1p[j] = s;
    } else if (i < P0_T16) {               // bvo = bv @ Wo + bo
        int j = i - P0_BVO;
        float s = bo[j];
#pragma unroll 8
        for (int k = 0; k < CH_; k++) s += bv[k] * Wo[k * CH_ + j];
        g_bvo[j] = s;
    } else if (i < P0_W1B) {               // t16 = bu @ Wld
        int j = i - P0_T16;
        float s = 0.f;
#pragma unroll 8
        for (int k = 0; k < C_; k++) s += bu[k] * Wld[k * RANK_ + j];
        g_t16[j] = s;
    } else if (i < P0_WGLU) {              // W1b = diag(dw_w) @ W1  (bf16)
        int j = i - P0_W1B;
        int k = j >> 8, n = j & 255;
        g_W1b[j] = __float2bfloat16_rn(dw_w[k] * W1[k * CH_ + n]);
    } else if (i < P0_TOTAL) {             // Wglu interleaved (bf16)
        int j = i - P0_WGLU;               // j < 1024*512
        int k = j >> 9, F = j & 511;
        int grp = F >> 4, wi = F & 15;
        int col = grp * 8 + (wi & 7);
        float v = (wi < 8) ? Wd[k * CH_ + col] : Wg[k * CH_ + col];
        g_Wglu[j] = __float2bfloat16_rn(v);
    }
}

// P1: fW23, fWuE, b23, buE
#define P1_FW23  0
#define P1_FWUE  65536
#define P1_B23   327680
#define P1_BUE   327936
#define P1_TOTAL 328960

__global__ void prep1(const float* __restrict__ W2, const float* __restrict__ Wu,
                      const float* __restrict__ Wlu, const float* __restrict__ b2,
                      const float* __restrict__ bu) {
    int i = blockIdx.x * blockDim.x + threadIdx.x;
    if (i < P1_FWUE) {                     // fW23 = W2 @ fWvo
        int r = i >> 8, c = i & 255;
        float s = 0.f;
#pragma unroll 8
        for (int k = 0; k < CH_; k++) s += W2[r * CH_ + k] * g_fWvo[k * CH_ + c];
        g_fW23[i] = s;
    } else if (i < P1_B23) {               // fWuE = Wu + fT1 @ Wlu
        int j = i - P1_FWUE;
        int r = j >> 10, c = j & 1023;
        float s = Wu[j];
#pragma unroll
        for (int k = 0; k < RANK_; k++) s += g_fT1[r * RANK_ + k] * Wlu[k * C_ + c];
        g_fWuE[j] = s;
    } else if (i < P1_BUE) {               // b23 = b2 @ fWvo + bvo
        int j = i - P1_B23;
        float s = g_bvo[j];
#pragma unroll 8
        for (int k = 0; k < CH_; k++) s += b2[k] * g_fWvo[k * CH_ + j];
        g_b23[j] = s;
    } else if (i < P1_TOTAL) {             // buE = bu + t16 @ Wlu
        int j = i - P1_BUE;
        float s = bu[j];
#pragma unroll
        for (int k = 0; k < RANK_; k++) s += g_t16[k] * Wlu[k * C_ + j];
        g_buE[j] = s;
    }
}

// P2a: fWt = fW23 @ fWuE
__global__ void prep2a() {
    int i = blockIdx.x * blockDim.x + threadIdx.x;
    if (i >= CH_ * C_) return;
    int r = i >> 10, c = i & 1023;
    float s = 0.f;
#pragma unroll 8
    for (int k = 0; k < CH_; k++) s += g_fW23[r * CH_ + k] * g_fWuE[k * C_ + c];
    g_fWt[i] = s;
}

// P2b: Wtb cast + bt
__global__ void prep2b() {
    int i = blockIdx.x * blockDim.x + threadIdx.x;
    if (i < CH_ * C_) {
        g_Wtb[i] = __float2bfloat16_rn(g_fWt[i]);
    } else if (i < CH_ * C_ + C_) {
        int j = i - CH_ * C_;
        float s = g_buE[j];
#pragma unroll 8
        for (int k = 0; k < CH_; k++) s += g_b23[k] * g_fWuE[k * C_ + j];
        g_bt[j] = s;
    }
}

// ---------------- LayerNorm -> bf16 ------------------------------------------
__global__ void ln_kernel(const float* __restrict__ x, const float* __restrict__ gamma,
                          const float* __restrict__ beta, __nv_bfloat16* __restrict__ z) {
    __shared__ float sh[16];
    int row = blockIdx.x;
    int tid = threadIdx.x;
    float4 v = ((const float4*)(x + (size_t)row * C_))[tid];
    float s  = v.x + v.y + v.z + v.w;
    float ss = v.x * v.x + v.y * v.y + v.z * v.z + v.w * v.w;
#pragma unroll
    for (int o = 16; o; o >>= 1) {
        s  += __shfl_xor_sync(0xFFFFFFFFu, s, o);
        ss += __shfl_xor_sync(0xFFFFFFFFu, ss, o);
    }
    int warp = tid >> 5;
    if ((tid & 31) == 0) { sh[warp] = s; sh[warp + 8] = ss; }
    __syncthreads();
    if (tid < 32) {
        float s2  = (tid < 8) ? sh[tid] : 0.f;
        float ss2 = (tid < 8) ? sh[tid + 8] : 0.f;
#pragma unroll
        for (int o = 4; o; o >>= 1) {
            s2  += __shfl_xor_sync(0xFFFFFFFFu, s2, o);
            ss2 += __shfl_xor_sync(0xFFFFFFFFu, ss2, o);
        }
        if (tid == 0) { sh[0] = s2; sh[1] = ss2; }
    }
    __syncthreads();
    float mean = sh[0] * (1.f / C_);
    float var  = sh[1] * (1.f / C_) - mean * mean;
    float rstd = rsqrtf(var + 1e-5f);
    float4 gm = ((const float4*)gamma)[tid];
    float4 bt = ((const float4*)beta)[tid];
    union { __nv_bfloat16 h[4]; uint2 u; } pk;
    pk.h[0] = __float2bfloat16_rn((v.x - mean) * rstd * gm.x + bt.x);
    pk.h[1] = __float2bfloat16_rn((v.y - mean) * rstd * gm.y + bt.y);
    pk.h[2] = __float2bfloat16_rn((v.z - mean) * rstd * gm.z + bt.z);
    pk.h[3] = __float2bfloat16_rn((v.w - mean) * rstd * gm.w + bt.w);
    ((uint2*)(z + (size_t)row * C_))[tid] = pk.u;
}

// ---------------- shared GEMM primitives -------------------------------------
__device__ __forceinline__ uint32_t smem_u32(const void* p) {
    return (uint32_t)__cvta_generic_to_shared(p);
}
__device__ __forceinline__ void cp16(uint32_t d, const void* s) {
    asm volatile("cp.async.cg.shared.global [%0], [%1], 16;\n" :: "r"(d), "l"(s));
}
__device__ __forceinline__ void cp_commit() { asm volatile("cp.async.commit_group;\n"); }
__device__ __forceinline__ void cp_wait2()  { asm volatile("cp.async.wait_group 2;\n"); }
__device__ __forceinline__ void ldsm_x4(uint32_t* r, uint32_t a) {
    asm volatile("ldmatrix.sync.aligned.m8n8.x4.shared.b16 {%0,%1,%2,%3}, [%4];\n"
                 : "=r"(r[0]), "=r"(r[1]), "=r"(r[2]), "=r"(r[3]) : "r"(a));
}
__device__ __forceinline__ void ldsm_x4_t(uint32_t* r, uint32_t a) {
    asm volatile("ldmatrix.sync.aligned.m8n8.x4.trans.shared.b16 {%0,%1,%2,%3}, [%4];\n"
                 : "=r"(r[0]), "=r"(r[1]), "=r"(r[2]), "=r"(r[3]) : "r"(a));
}
__device__ __forceinline__ void mma16816(float* c, const uint32_t* a, const uint32_t* b) {
    asm volatile(
        "mma.sync.aligned.m16n8k16.row.col.f32.bf16.bf16.f32 "
        "{%0,%1,%2,%3}, {%4,%5,%6,%7}, {%8,%9}, {%0,%1,%2,%3};\n"
        : "+f"(c[0]), "+f"(c[1]), "+f"(c[2]), "+f"(c[3])
        : "r"(a[0]), "r"(a[1]), "r"(a[2]), "r"(a[3]), "r"(b[0]), "r"(b[1]));
}
__device__ __forceinline__ float gelu_tanh(float t) {
    float t3 = t * t * t;
    return 0.5f * t * (1.0f + tanhf(0.7978845608028654f * (t + 0.044715f * t3)));
}

// ---------------- fused GLU GEMM ----------------------------------------------
// u[128-row tile, 128 out cols] from z[128,1024] @ Wglu[1024, 512-fused]
// BM=128, BNf=256 fused cols (=128 real cols), BK=32, 3-stage cp.async,
// 512 threads / 16 warps (2 warpM x 8 warpN), warp tile 64 x 32 fused cols.
// Weight interleave: per 16 fused cols = [8 d-cols | 8 g-cols] of same 8 outputs.
#define GSTG 24576          // stage bytes: A 8192 + B 16384
#define GB_OFF 8192

__global__ __launch_bounds__(512)
void gemm_glu(const __nv_bfloat16* __restrict__ A, const __nv_bfloat16* __restrict__ W,
              const float* __restrict__ bd, const float* __restrict__ bg,
              __nv_bfloat16* __restrict__ out) {
    extern __shared__ __align__(1024) char dsm[];
    const int tid  = threadIdx.x;
    const int warp = tid >> 5, lane = tid & 31;
    const int warpM = warp & 1;       // 64 rows
    const int warpN = warp >> 1;      // 0..7, 32 fused cols
    const int bm  = blockIdx.y * 128;
    const int bnf = blockIdx.x * 256;
    const uint32_t sb = smem_u32(dsm);

    // A store: 1 x cp16 per thread
    const int ar = tid >> 2, ac = tid & 3;
    const uint32_t aSt = (uint32_t)(ar * 32 + ((ac ^ ((ar >> 1) & 3)) << 3)) * 2;
    const __nv_bfloat16* pa = A + (size_t)(bm + ar) * C_ + ac * 8;
    // B store: 2 x cp16 per thread (rows kb, kb+16)
    const int kb = tid >> 5, cb = tid & 31;
    const uint32_t bSw0 = (uint32_t)(kb * 256 + ((cb >> 3) << 6) + (((cb & 7) ^ (kb & 7)) << 3)) * 2;
    const uint32_t bSw1 = (uint32_t)((kb + 16) * 256 + ((cb >> 3) << 6) + (((cb & 7) ^ (kb & 7)) << 3)) * 2;
    const __nv_bfloat16* pb = W + (size_t)kb * 512 + bnf + cb * 8;
    const size_t pbRow16 = (size_t)16 * 512;
    const size_t pbStep  = (size_t)32 * 512;

    float acc[4][4][4];
#pragma unroll
    for (int a0 = 0; a0 < 4; a0++)
#pragma unroll
        for (int a1 = 0; a1 < 4; a1++)
#pragma unroll
            for (int a2 = 0; a2 < 4; a2++) acc[a0][a1][a2] = 0.f;

    const int l15 = lane & 15, hi = lane >> 4, l7 = lane & 7;
    int rowA[4], swzA[4];
#pragma unroll
    for (int mt = 0; mt < 4; mt++) {
        rowA[mt] = warpM * 64 + mt * 16 + l15;
        swzA[mt] = (rowA[mt] >> 1) & 3;
    }

    const int KT = C_ >> 5;   // 32

    // prologue: stages 0,1
#pragma unroll
    for (int t = 0; t < 2; t++) {
        uint32_t base = sb + t * GSTG;
        cp16(base + aSt, pa + t * 32);
        cp16(base + GB_OFF + bSw0, pb + (size_t)t * pbStep);
        cp16(base + GB_OFF + bSw1, pb + (size_t)t * pbStep + pbRow16);
        cp_commit();
    }

    int sL = 2, sC = 0;
    for (int kt = 0; kt < KT; kt++) {
        if (kt + 2 < KT) {
            uint32_t base = sb + sL * GSTG;
            cp16(base + aSt, pa + (kt + 2) * 32);
            cp16(base + GB_OFF + bSw0, pb + (size_t)(kt + 2) * pbStep);
            cp16(base + GB_OFF + bSw1, pb + (size_t)(kt + 2) * pbStep + pbRow16);
        }
        cp_commit();
        cp_wait2();
        __syncthreads();

        const uint32_t sA = sb + sC * GSTG;
        const uint32_t sB = sA + GB_OFF;
#pragma unroll
        for (int ks = 0; ks < 2; ks++) {
            uint32_t aF[4][4];
#pragma unroll
            for (int mt = 0; mt < 4; mt++) {
                uint32_t addr = sA + (uint32_t)(rowA[mt] * 32 +
                                  (((ks * 2 + hi) ^ swzA[mt]) << 3)) * 2;
                ldsm_x4(aF[mt], addr);
            }
            uint32_t bF[8];
#pragma unroll
            for (int half = 0; half < 2; half++) {
                int q = warpN * 4 + half * 2 + hi;
                uint32_t addr = sB + (uint32_t)((ks * 16 + l15) * 256 +
                                  ((q >> 3) << 6) + (((q & 7) ^ l7) << 3)) * 2;
                ldsm_x4_t(&bF[half * 4], addr);
            }
#pragma unroll
            for (int mt = 0; mt < 4; mt++)
#pragma unroll
                for (int nt = 0; nt < 4; nt++)
                    mma16816(acc[mt][nt], aF[mt], &bF[nt * 2]);
        }
        __syncthreads();
        sL = (sL == 2) ? 0 : sL + 1;
        sC = (sC == 2) ? 0 : sC + 1;
    }

    // epilogue: GLU in registers; nt pairs (0,1) and (2,3)
    const int g = lane >> 2, tig = lane & 3;
#pragma unroll
    for (int mt = 0; mt < 4; mt++) {
#pragma unroll
        for (int j = 0; j < 2; j++) {
            int F = bnf + warpN * 32 + j * 16 + tig * 2;   // fused d col (F&15 < 8)
            int oc = ((F >> 4) << 3) + (F & 7);            // real out col
            float bdc0 = bd[oc], bdc1 = bd[oc + 1];
            float bgc0 = bg[oc], bgc1 = bg[oc + 1];
#pragma unroll
            for (int h = 0; h < 2; h++) {
                int row = bm + warpM * 64 + mt * 16 + g + h * 8;
                float d0 = acc[mt][2 * j][2 * h]     + bdc0;
                float d1 = acc[mt][2 * j][2 * h + 1] + bdc1;
                float g0 = acc[mt][2 * j + 1][2 * h]     + bgc0;
                float g1 = acc[mt][2 * j + 1][2 * h + 1] + bgc1;
                float s0 = 1.0f / (1.0f + expf(-g0));
                float s1 = 1.0f / (1.0f + expf(-g1));
                __nv_bfloat162 o;
                o.x = __float2bfloat16_rn(d0 * s0);
                o.y = __float2bfloat16_rn(d1 * s1);
                *reinterpret_cast<__nv_bfloat162*>(out + (size_t)row * CH_ + oc) = o;
            }
        }
    }
}

// ---------------- standard bf16 GEMM (proven R2 kernel) -----------------------
// EPI 2: bias + gelu -> bf16 | EPI 4: bias + 0.5/0.5 residual(aux) -> f32
#define ASTAGE 8192
#define BSTAGE 8192

template <int EPI>
__global__ __launch_bounds__(256, 2)
void gemm_bf16(const __nv_bfloat16* __restrict__ A, const __nv_bfloat16* __restrict__ W,
               int M, int N, int K,
               const float* __restrict__ bias,
               const float* __restrict__ aux, void* __restrict__ Cout) {
    __shared__ __nv_bfloat16 As[3 * 4096];
    __shared__ __nv_bfloat16 Bt[3 * 4096];

    const int tid  = threadIdx.x;
    const int warp = tid >> 5, lane = tid & 31;
    const int warpM = warp & 1;
    const int warpN = warp >> 1;
    const int bm = blockIdx.y * 128;
    const int bn = blockIdx.x * 128;

    const int r  = tid >> 2;
    const int c  = tid & 3;
    const int kb = tid >> 4;
    const int cb = tid & 15;
    const uint32_t sAb = smem_u32(As);
    const uint32_t sBb = smem_u32(Bt);
    const uint32_t aSt0 = sAb + (uint32_t)(r * 32 + ((c ^ ((r >> 1) & 3)) << 3)) * 2;
    const uint32_t aSt1 = sAb + (uint32_t)((r + 64) * 32 + ((c ^ ((r >> 1) & 3)) << 3)) * 2;
    const uint32_t bSt0 = sBb + (uint32_t)(kb * 128 + ((cb ^ (kb & 7)) << 3)) * 2;
    const uint32_t bSt1 = sBb + (uint32_t)((kb + 16) * 128 + ((cb ^ (kb & 7)) << 3)) * 2;

    const __nv_bfloat16* pa = A + (size_t)(bm + r) * K + c * 8;
    const __nv_bfloat16* pb = W + (size_t)kb * N + bn + cb * 8;
    const size_t paRow64 = (size_t)64 * K;
    const size_t pbRow16 = (size_t)16 * N;
    const size_t pbStep  = (size_t)32 * N;

    float acc[4][4][4];
#pragma unroll
    for (int a0 = 0; a0 < 4; a0++)
#pragma unroll
        for (int a1 = 0; a1 < 4; a1++)
#pragma unroll
            for (int a2 = 0; a2 < 4; a2++) acc[a0][a1][a2] = 0.f;

    const int l15 = lane & 15, hi = lane >> 4, l7 = lane & 7;
    int rowA[4], swzA[4];
#pragma unroll
    for (int mt = 0; mt < 4; mt++) {
        rowA[mt] = warpM * 64 + mt * 16 + l15;
        swzA[mt] = (rowA[mt] >> 1) & 3;
    }

    const int KT = K >> 5;

    cp16(aSt0, pa); cp16(aSt1, pa + paRow64);
    cp16(bSt0, pb); cp16(bSt1, pb + pbRow16);
    cp_commit();
    pa += 32; pb += pbStep;
    cp16(aSt0 + ASTAGE, pa); cp16(aSt1 + ASTAGE, pa + paRow64);
    cp16(bSt0 + BSTAGE, pb); cp16(bSt1 + BSTAGE, pb + pbRow16);
    cp_commit();
    pa += 32; pb += pbStep;

    int sL = 2, sC = 0;
    for (int kt = 0; kt < KT; kt++) {
        if (kt + 2 < KT) {
            uint32_t ao = (uint32_t)sL * ASTAGE, bo = (uint32_t)sL * BSTAGE;
            cp16(aSt0 + ao, pa); cp16(aSt1 + ao, pa + paRow64);
            cp16(bSt0 + bo, pb); cp16(bSt1 + bo, pb + pbRow16);
            pa += 32; pb += pbStep;
        }
        cp_commit();
        cp_wait2();
        __syncthreads();

        const uint32_t sA = sAb + (uint32_t)sC * ASTAGE;
        const uint32_t sB = sBb + (uint32_t)sC * BSTAGE;
#pragma unroll
        for (int ks = 0; ks < 2; ks++) {
            uint32_t aF[4][4];
#pragma unroll
            for (int mt = 0; mt < 4; mt++) {
                uint32_t addr = sA + (uint32_t)(rowA[mt] * 32 +
                                  (((ks * 2 + hi) ^ swzA[mt]) << 3)) * 2;
                ldsm_x4(aF[mt], addr);
            }
            uint32_t bF[8];
#pragma unroll
            for (int half = 0; half < 2; half++) {
                int c0 = warpN * 4 + half * 2;
                uint32_t addr = sB + (uint32_t)((ks * 16 + l15) * 128 +
                                  (((c0 + hi) ^ l7) << 3)) * 2;
                ldsm_x4_t(&bF[half * 4], addr);
            }
#pragma unroll
            for (int mt = 0; mt < 4; mt++)
#pragma unroll
                for (int nt = 0; nt < 4; nt++)
                    mma16816(acc[mt][nt], aF[mt], &bF[nt * 2]);
        }
        __syncthreads();
        sL = (sL == 2) ? 0 : sL + 1;
        sC = (sC == 2) ? 0 : sC + 1;
    }

    const int g = lane >> 2, tig = lane & 3;
#pragma unroll
    for (int mt = 0; mt < 4; mt++) {
#pragma unroll
        for (int nt = 0; nt < 4; nt++) {
            int col = bn + warpN * 32 + nt * 8 + tig * 2;
#pragma unroll
            for (int h = 0; h < 2; h++) {
                int row = bm + warpM * 64 + mt * 16 + g + h * 8;
                float v0 = acc[mt][nt][2 * h], v1 = acc[mt][nt][2 * h + 1];
                size_t oi = (size_t)row * N + col;
                if (EPI == 2) {
                    __nv_bfloat162 o;
                    o.x = __float2bfloat16_rn(gelu_tanh(v0 + bias[col]));
                    o.y = __float2bfloat16_rn(gelu_tanh(v1 + bias[col + 1]));
                    *reinterpret_cast<__nv_bfloat162*>((__nv_bfloat16*)Cout + oi) = o;
                } else {  // 4
                    float2 a2 = *reinterpret_cast<const float2*>(aux + oi);
                    float2 o = make_float2(0.5f * (v0 + bias[col]) + 0.5f * a2.x,
                                           0.5f * (v1 + bias[col + 1]) + 0.5f * a2.y);
                    *reinterpret_cast<float2*>((float*)Cout + oi) = o;
                }
            }
        }
    }
}

// ---------------- launch ------------------------------------------------------
static void* sym(const void* s) {
    void* p = nullptr;
    cudaGetSymbolAddress(&p, s);
    return p;
}

extern "C" void kernel_launch(void* const* d_in, const int* in_sizes, int n_in,
                              void* d_out, int out_size) {
    const float* x    = (const float*)d_in[0];
    const float* ln_g = (const float*)d_in[1];
    const float* ln_b = (const float*)d_in[2];
    const float* Wd   = (const float*)d_in[3];
    const float* bd   = (const float*)d_in[4];
    const float* Wg   = (const float*)d_in[5];
    const float* bg   = (const float*)d_in[6];
    const float* dw_w = (const float*)d_in[7];
    const float* dw_b = (const float*)d_in[8];
    const float* W1   = (const float*)d_in[9];
    const float* b1   = (const float*)d_in[10];
    const float* W2   = (const float*)d_in[11];
    const float* b2   = (const float*)d_in[12];
    // d_in[13..16] = Wq,bq,Wk,bk : dead (softmax over one key == 1)
    const float* Wv   = (const float*)d_in[17];
    const float* bv   = (const float*)d_in[18];
    const float* Wo   = (const float*)d_in[19];
    const float* bo   = (const float*)d_in[20];
    const float* Wu   = (const float*)d_in[21];
    const float* bu   = (const float*)d_in[22];
    const float* Wld  = (const float*)d_in[23];
    const float* Wlu  = (const float*)d_in[24];
    float* out = (float*)d_out;

    __nv_bfloat16* zW   = (__nv_bfloat16*)sym(g_z);
    __nv_bfloat16* uW   = (__nv_bfloat16*)sym(g_u);
    __nv_bfloat16* pW   = (__nv_bfloat16*)sym(g_p);
    __nv_bfloat16* Wglu = (__nv_bfloat16*)sym(g_Wglu);
    __nv_bfloat16* W1b  = (__nv_bfloat16*)sym(g_W1b);
    __nv_bfloat16* Wtb  = (__nv_bfloat16*)sym(g_Wtb);
    float* b1p = (float*)sym(g_b1p);
    float* bt  = (float*)sym(g_bt);

    // prep (4 launches)
    prep0<<<(P0_TOTAL + 255) / 256, 256>>>(Wv, Wo, bo, Wu, Wld, dw_w, dw_b, W1, b1, bv, bu, Wd, Wg);
    prep1<<<(P1_TOTAL + 255) / 256, 256>>>(W2, Wu, Wlu, b2, bu);
    prep2a<<<(CH_ * C_ + 255) / 256, 256>>>();
    prep2b<<<(CH_ * C_ + C_ + 255) / 256, 256>>>();

    // LN
    ln_kernel<<<B_, 256>>>(x, ln_g, ln_b, zW);

    // fused GLU GEMM (ncu -s5 capture slot)
    static int glu_attr_set = 0;
    cudaFuncSetAttribute(gemm_glu, cudaFuncAttributeMaxDynamicSharedMemorySize, 3 * GSTG);
    gemm_glu<<<dim3(2, B_ / 128), 512, 3 * GSTG>>>(zW, Wglu, bd, bg, uW);
    (void)glu_attr_set;

    // gelu GEMM
    gemm_bf16<2><<<dim3(CH_ / 128, B_ / 128), 256>>>(uW, W1b, B_, CH_, CH_, b1p, nullptr, pW);

    // tail GEMM + residual
    gemm_bf16<4><<<dim3(C_ / 128, B_ / 128), 256>>>(pW, Wtb, B_, C_, CH_, bt, x, out);
}

// round 6
// speedup vs baseline: 3.5533x; 1.1361x over previous
#include <cuda_runtime.h>
#include <cuda_bf16.h>
#include <math.h>
#include <stdint.h>

#define B_  32768
#define C_  1024
#define CH_ 256
#define RANK_ 16

// ---------------- scratch (device globals; no allocation allowed) ------------
__device__ __nv_bfloat16 g_z [B_ * C_];     // LN output
__device__ __nv_bfloat16 g_u [B_ * CH_];    // GLU output
__device__ __nv_bfloat16 g_p [B_ * CH_];    // gelu output

__device__ __nv_bfloat16 g_Wglu[C_ * 512];  // [K=1024][512] interleaved 8d|8g per 16
__device__ __nv_bfloat16 g_W1b [CH_ * CH_]; // [K=256][N=256] dw-folded W1
__device__ __nv_bfloat16 g_Wtb [CH_ * C_];  // [K=256][N=1024] Wtail (bf16)

__device__ float g_fWvo[CH_ * CH_];
__device__ float g_fW23[CH_ * CH_];
__device__ float g_fT1 [CH_ * RANK_];
__device__ float g_fWuE[CH_ * C_];
__device__ float g_b1p[CH_], g_bvo[CH_], g_t16[RANK_], g_b23[CH_], g_buE[C_], g_bt[C_];

__device__ __forceinline__ float warp_sum(float s) {
#pragma unroll
    for (int o = 16; o; o >>= 1) s += __shfl_xor_sync(0xFFFFFFFFu, s, o);
    return s;
}

// ---------------- prepA: fWvo, fT1, b1p, bvo, t16, W1b, Wglu ------------------
#define A_FWVO 0
#define A_FT1  65536
#define A_B1P  196608
#define A_BVO  204800
#define A_T16  212992
#define A_W1B  213504
#define A_WGLU 279040
#define A_TOT  803328   // = 3138 * 256

__global__ void prepA(const float* __restrict__ Wv, const float* __restrict__ Wo,
                      const float* __restrict__ bo, const float* __restrict__ Wu,
                      const float* __restrict__ Wld, const float* __restrict__ dw_w,
                      const float* __restrict__ dw_b, const float* __restrict__ W1,
                      const float* __restrict__ b1, const float* __restrict__ bv,
                      const float* __restrict__ bu, const float* __restrict__ Wd,
                      const float* __restrict__ Wg) {
    int i = blockIdx.x * blockDim.x + threadIdx.x;
    if (i >= A_TOT) return;
    int lane = i & 31;
    if (i < A_FT1) {                       // fWvo = Wv @ Wo (naive, coalesced c)
        int r = i >> 8, c = i & 255;
        float s = 0.f;
#pragma unroll 8
        for (int k = 0; k < CH_; k++) s += Wv[r * CH_ + k] * Wo[k * CH_ + c];
        g_fWvo[i] = s;
    } else if (i < A_B1P) {                // fT1 = Wu @ Wld (warp-split K=1024)
        int w = (i - A_FT1) >> 5;          // 0..4095
        int r = w >> 4, c = w & 15;
        float s = 0.f;
#pragma unroll
        for (int kk = 0; kk < 32; kk++) {
            int k = lane + kk * 32;
            s += Wu[r * C_ + k] * Wld[k * RANK_ + c];
        }
        s = warp_sum(s);
        if (lane == 0) g_fT1[w] = s;
    } else if (i < A_BVO) {                // b1p = dw_b @ W1 + b1 (warp-split K=256)
        int w = (i - A_B1P) >> 5;          // 0..255
        float s = 0.f;
#pragma unroll
        for (int kk = 0; kk < 8; kk++) {
            int k = lane + kk * 32;
            s += dw_b[k] * W1[k * CH_ + w];
        }
        s = warp_sum(s);
        if (lane == 0) g_b1p[w] = s + b1[w];
    } else if (i < A_T16) {                // bvo = bv @ Wo + bo (warp-split)
        int w = (i - A_BVO) >> 5;
        float s = 0.f;
#pragma unroll
        for (int kk = 0; kk < 8; kk++) {
            int k = lane + kk * 32;
            s += bv[k] * Wo[k * CH_ + w];
        }
        s = warp_sum(s);
        if (lane == 0) g_bvo[w] = s + bo[w];
    } else if (i < A_W1B) {                // t16 = bu @ Wld (warp-split K=1024)
        int w = (i - A_T16) >> 5;          // 0..15
        float s = 0.f;
#pragma unroll
        for (int kk = 0; kk < 32; kk++) {
            int k = lane + kk * 32;
            s += bu[k] * Wld[k * RANK_ + w];
        }
        s = warp_sum(s);
        if (lane == 0) g_t16[w] = s;
    } else if (i < A_WGLU) {               // W1b = diag(dw_w) @ W1 (bf16)
        int j = i - A_W1B;
        int k = j >> 8, n = j & 255;
        g_W1b[j] = __float2bfloat16_rn(dw_w[k] * W1[k * CH_ + n]);
    } else {                               // Wglu interleaved (bf16)
        int j = i - A_WGLU;                // < 1024*512
        int k = j >> 9, F = j & 511;
        int grp = F >> 4, wi = F & 15;
        int col = grp * 8 + (wi & 7);
        float v = (wi < 8) ? Wd[k * CH_ + col] : Wg[k * CH_ + col];
        g_Wglu[j] = __float2bfloat16_rn(v);
    }
}

// ---------------- prepB: fW23, fWuE, b23, buE ---------------------------------
#define B_FW23 0
#define B_FWUE 65536
#define B_B23  327680
#define B_BUE  335872
#define B_TOT  336896   // = 1316 * 256

__global__ void prepB(const float* __restrict__ W2, const float* __restrict__ Wu,
                      const float* __restrict__ Wlu, const float* __restrict__ b2,
                      const float* __restrict__ bu) {
    int i = blockIdx.x * blockDim.x + threadIdx.x;
    if (i >= B_TOT) return;
    int lane = i & 31;
    if (i < B_FWUE) {                      // fW23 = W2 @ fWvo
        int r = i >> 8, c = i & 255;
        float s = 0.f;
#pragma unroll 8
        for (int k = 0; k < CH_; k++) s += W2[r * CH_ + k] * g_fWvo[k * CH_ + c];
        g_fW23[i] = s;
    } else if (i < B_B23) {                // fWuE = Wu + fT1 @ Wlu (K=16)
        int j = i - B_FWUE;
        int r = j >> 10, c = j & 1023;
        float s = Wu[j];
#pragma unroll
        for (int k = 0; k < RANK_; k++) s += g_fT1[r * RANK_ + k] * Wlu[k * C_ + c];
        g_fWuE[j] = s;
    } else if (i < B_BUE) {                // b23 = b2 @ fWvo + bvo (warp-split)
        int w = (i - B_B23) >> 5;
        float s = 0.f;
#pragma unroll
        for (int kk = 0; kk < 8; kk++) {
            int k = lane + kk * 32;
            s += b2[k] * g_fWvo[k * CH_ + w];
        }
        s = warp_sum(s);
        if (lane == 0) g_b23[w] = s + g_bvo[w];
    } else {                               // buE = bu + t16 @ Wlu (K=16)
        int j = i - B_BUE;
        float s = bu[j];
#pragma unroll
        for (int k = 0; k < RANK_; k++) s += g_t16[k] * Wlu[k * C_ + j];
        g_buE[j] = s;
    }
}

// ---------------- prepC: Wtb = bf16(fW23 @ fWuE), bt --------------------------
// blocks 0..63: tiled SGEMM M=256,N=1024,K=256 in 64x64 tiles -> bf16 store
// blocks 64..67: bt = b23 @ fWuE + buE (warp-split)
__global__ __launch_bounds__(256)
void prepC() {
    int bid = blockIdx.x;
    int tid = threadIdx.x;
    if (bid < 64) {
        __shared__ float As[64][33];
        __shared__ float Bs[32][65];
        int by = bid >> 4, bx = bid & 15;
        int ty = tid >> 4, tx = tid & 15;
        float acc[4][4];
#pragma unroll
        for (int a = 0; a < 4; a++)
#pragma unroll
            for (int b = 0; b < 4; b++) acc[a][b] = 0.f;
        for (int kc = 0; kc < 8; kc++) {
#pragma unroll
            for (int j = 0; j < 8; j++) {
                int e = tid + j * 256;          // A: 64x32
                int m = e >> 5, k = e & 31;
                As[m][k] = g_fW23[(by * 64 + m) * CH_ + kc * 32 + k];
            }
#pragma unroll
            for (int j = 0; j < 8; j++) {
                int e = tid + j * 256;          // B: 32x64
                int k = e >> 6, n = e & 63;
                Bs[k][n] = g_fWuE[(kc * 32 + k) * C_ + bx * 64 + n];
            }
            __syncthreads();
#pragma unroll
            for (int k = 0; k < 32; k++) {
                float a0 = As[ty * 4 + 0][k], a1 = As[ty * 4 + 1][k];
                float a2 = As[ty * 4 + 2][k], a3 = As[ty * 4 + 3][k];
                float b0 = Bs[k][tx * 4 + 0], b1 = Bs[k][tx * 4 + 1];
                float b2 = Bs[k][tx * 4 + 2], b3 = Bs[k][tx * 4 + 3];
                acc[0][0] += a0 * b0; acc[0][1] += a0 * b1; acc[0][2] += a0 * b2; acc[0][3] += a0 * b3;
                acc[1][0] += a1 * b0; acc[1][1] += a1 * b1; acc[1][2] += a1 * b2; acc[1][3] += a1 * b3;
                acc[2][0] += a2 * b0; acc[2][1] += a2 * b1; acc[2][2] += a2 * b2; acc[2][3] += a2 * b3;
                acc[3][0] += a3 * b0; acc[3][1] += a3 * b1; acc[3][2] += a3 * b2; acc[3][3] += a3 * b3;
            }
            __syncthreads();
        }
#pragma unroll
        for (int a = 0; a < 4; a++) {
            int row = by * 64 + ty * 4 + a;
#pragma unroll
            for (int b = 0; b < 4; b++) {
                int col = bx * 64 + tx * 4 + b;
                g_Wtb[row * C_ + col] = __float2bfloat16_rn(acc[a][b]);
            }
        }
    } else {
        int w = (bid - 64) * 8 + (tid >> 5);   // 0..31
        int lane = tid & 31;
        for (int jj = 0; jj < 32; jj++) {
            int j = w * 32 + jj;
            float s = 0.f;
#pragma unroll
            for (int kk = 0; kk < 8; kk++) {
                int k = lane + kk * 32;
                s += g_b23[k] * g_fWuE[k * C_ + j];
            }
            s = warp_sum(s);
            if (lane == 0) g_bt[j] = s + g_buE[j];
        }
    }
}

// ---------------- LayerNorm -> bf16 ------------------------------------------
__global__ void ln_kernel(const float* __restrict__ x, const float* __restrict__ gamma,
                          const float* __restrict__ beta, __nv_bfloat16* __restrict__ z) {
    __shared__ float sh[16];
    int row = blockIdx.x;
    int tid = threadIdx.x;
    float4 v = ((const float4*)(x + (size_t)row * C_))[tid];
    float s  = v.x + v.y + v.z + v.w;
    float ss = v.x * v.x + v.y * v.y + v.z * v.z + v.w * v.w;
#pragma unroll
    for (int o = 16; o; o >>= 1) {
        s  += __shfl_xor_sync(0xFFFFFFFFu, s, o);
        ss += __shfl_xor_sync(0xFFFFFFFFu, ss, o);
    }
    int warp = tid >> 5;
    if ((tid & 31) == 0) { sh[warp] = s; sh[warp + 8] = ss; }
    __syncthreads();
    if (tid < 32) {
        float s2  = (tid < 8) ? sh[tid] : 0.f;
        float ss2 = (tid < 8) ? sh[tid + 8] : 0.f;
#pragma unroll
        for (int o = 4; o; o >>= 1) {
            s2  += __shfl_xor_sync(0xFFFFFFFFu, s2, o);
            ss2 += __shfl_xor_sync(0xFFFFFFFFu, ss2, o);
        }
        if (tid == 0) { sh[0] = s2; sh[1] = ss2; }
    }
    __syncthreads();
    float mean = sh[0] * (1.f / C_);
    float var  = sh[1] * (1.f / C_) - mean * mean;
    float rstd = rsqrtf(var + 1e-5f);
    float4 gm = ((const float4*)gamma)[tid];
    float4 bt = ((const float4*)beta)[tid];
    union { __nv_bfloat16 h[4]; uint2 u; } pk;
    pk.h[0] = __float2bfloat16_rn((v.x - mean) * rstd * gm.x + bt.x);
    pk.h[1] = __float2bfloat16_rn((v.y - mean) * rstd * gm.y + bt.y);
    pk.h[2] = __float2bfloat16_rn((v.z - mean) * rstd * gm.z + bt.z);
    pk.h[3] = __float2bfloat16_rn((v.w - mean) * rstd * gm.w + bt.w);
    ((uint2*)(z + (size_t)row * C_))[tid] = pk.u;
}

// ---------------- shared GEMM primitives -------------------------------------
__device__ __forceinline__ uint32_t smem_u32(const void* p) {
    return (uint32_t)__cvta_generic_to_shared(p);
}
__device__ __forceinline__ void cp16(uint32_t d, const void* s) {
    asm volatile("cp.async.cg.shared.global [%0], [%1], 16;\n" :: "r"(d), "l"(s));
}
__device__ __forceinline__ void cp_commit() { asm volatile("cp.async.commit_group;\n"); }
__device__ __forceinline__ void cp_wait1()  { asm volatile("cp.async.wait_group 1;\n"); }
__device__ __forceinline__ void ldsm_x4(uint32_t* r, uint32_t a) {
    asm volatile("ldmatrix.sync.aligned.m8n8.x4.shared.b16 {%0,%1,%2,%3}, [%4];\n"
                 : "=r"(r[0]), "=r"(r[1]), "=r"(r[2]), "=r"(r[3]) : "r"(a));
}
__device__ __forceinline__ void ldsm_x4_t(uint32_t* r, uint32_t a) {
    asm volatile("ldmatrix.sync.aligned.m8n8.x4.trans.shared.b16 {%0,%1,%2,%3}, [%4];\n"
                 : "=r"(r[0]), "=r"(r[1]), "=r"(r[2]), "=r"(r[3]) : "r"(a));
}
__device__ __forceinline__ void mma16816(float* c, const uint32_t* a, const uint32_t* b) {
    asm volatile(
        "mma.sync.aligned.m16n8k16.row.col.f32.bf16.bf16.f32 "
        "{%0,%1,%2,%3}, {%4,%5,%6,%7}, {%8,%9}, {%0,%1,%2,%3};\n"
        : "+f"(c[0]), "+f"(c[1]), "+f"(c[2]), "+f"(c[3])
        : "r"(a[0]), "r"(a[1]), "r"(a[2]), "r"(a[3]), "r"(b[0]), "r"(b[1]));
}
__device__ __forceinline__ float gelu_tanh(float t) {
    float t3 = t * t * t;
    return 0.5f * t * (1.0f + tanhf(0.7978845608028654f * (t + 0.044715f * t3)));
}

// ---------------- fused GLU GEMM (single-sync 3-stage) ------------------------
#define GSTG 24576
#define GB_OFF 8192

__global__ __launch_bounds__(512)
void gemm_glu(const __nv_bfloat16* __restrict__ A, const __nv_bfloat16* __restrict__ W,
              const float* __restrict__ bd, const float* __restrict__ bg,
              __nv_bfloat16* __restrict__ out) {
    extern __shared__ __align__(1024) char dsm[];
    const int tid  = threadIdx.x;
    const int warp = tid >> 5, lane = tid & 31;
    const int warpM = warp & 1;
    const int warpN = warp >> 1;
    const int bm  = blockIdx.y * 128;
    const int bnf = blockIdx.x * 256;
    const uint32_t sb = smem_u32(dsm);

    const int ar = tid >> 2, ac = tid & 3;
    const uint32_t aSt = (uint32_t)(ar * 32 + ((ac ^ ((ar >> 1) & 3)) << 3)) * 2;
    const __nv_bfloat16* pa = A + (size_t)(bm + ar) * C_ + ac * 8;
    const int kb = tid >> 5, cb = tid & 31;
    const uint32_t bSw0 = (uint32_t)(kb * 256 + ((cb >> 3) << 6) + (((cb & 7) ^ (kb & 7)) << 3)) * 2;
    const uint32_t bSw1 = (uint32_t)((kb + 16) * 256 + ((cb >> 3) << 6) + (((cb & 7) ^ (kb & 7)) << 3)) * 2;
    const __nv_bfloat16* pb = W + (size_t)kb * 512 + bnf + cb * 8;
    const size_t pbRow16 = (size_t)16 * 512;
    const size_t pbStep  = (size_t)32 * 512;

    float acc[4][4][4];
#pragma unroll
    for (int a0 = 0; a0 < 4; a0++)
#pragma unroll
        for (int a1 = 0; a1 < 4; a1++)
#pragma unroll
            for (int a2 = 0; a2 < 4; a2++) acc[a0][a1][a2] = 0.f;

    const int l15 = lane & 15, hi = lane >> 4, l7 = lane & 7;
    int rowA[4], swzA[4];
#pragma unroll
    for (int mt = 0; mt < 4; mt++) {
        rowA[mt] = warpM * 64 + mt * 16 + l15;
        swzA[mt] = (rowA[mt] >> 1) & 3;
    }

    const int KT = C_ >> 5;   // 32

#pragma unroll
    for (int t = 0; t < 2; t++) {
        uint32_t base = sb + t * GSTG;
        cp16(base + aSt, pa + t * 32);
        cp16(base + GB_OFF + bSw0, pb + (size_t)t * pbStep);
        cp16(base + GB_OFF + bSw1, pb + (size_t)t * pbStep + pbRow16);
        cp_commit();
    }

    int sL = 2, sC = 0;
    for (int kt = 0; kt < KT; kt++) {
        cp_wait1();
        __syncthreads();
        if (kt + 2 < KT) {
            uint32_t base = sb + sL * GSTG;
            cp16(base + aSt, pa + (kt + 2) * 32);
            cp16(base + GB_OFF + bSw0, pb + (size_t)(kt + 2) * pbStep);
            cp16(base + GB_OFF + bSw1, pb + (size_t)(kt + 2) * pbStep + pbRow16);
        }
        cp_commit();

        const uint32_t sA = sb + sC * GSTG;
        const uint32_t sB = sA + GB_OFF;
#pragma unroll
        for (int ks = 0; ks < 2; ks++) {
            uint32_t aF[4][4];
#pragma unroll
            for (int mt = 0; mt < 4; mt++) {
                uint32_t addr = sA + (uint32_t)(rowA[mt] * 32 +
                                  (((ks * 2 + hi) ^ swzA[mt]) << 3)) * 2;
                ldsm_x4(aF[mt], addr);
            }
            uint32_t bF[8];
#pragma unroll
            for (int half = 0; half < 2; half++) {
                int q = warpN * 4 + half * 2 + hi;
                uint32_t addr = sB + (uint32_t)((ks * 16 + l15) * 256 +
                                  ((q >> 3) << 6) + (((q & 7) ^ l7) << 3)) * 2;
                ldsm_x4_t(&bF[half * 4], addr);
            }
#pragma unroll
            for (int mt = 0; mt < 4; mt++)
#pragma unroll
                for (int nt = 0; nt < 4; nt++)
                    mma16816(acc[mt][nt], aF[mt], &bF[nt * 2]);
        }
        sL = (sL == 2) ? 0 : sL + 1;
        sC = (sC == 2) ? 0 : sC + 1;
    }

    const int g = lane >> 2, tig = lane & 3;
#pragma unroll
    for (int mt = 0; mt < 4; mt++) {
#pragma unroll
        for (int j = 0; j < 2; j++) {
            int F = bnf + warpN * 32 + j * 16 + tig * 2;
            int oc = ((F >> 4) << 3) + (F & 7);
            float bdc0 = bd[oc], bdc1 = bd[oc + 1];
            float bgc0 = bg[oc], bgc1 = bg[oc + 1];
#pragma unroll
            for (int h = 0; h < 2; h++) {
                int row = bm + warpM * 64 + mt * 16 + g + h * 8;
                float d0 = acc[mt][2 * j][2 * h]     + bdc0;
                float d1 = acc[mt][2 * j][2 * h + 1] + bdc1;
                float g0 = acc[mt][2 * j + 1][2 * h]     + bgc0;
                float g1 = acc[mt][2 * j + 1][2 * h + 1] + bgc1;
                float s0 = 1.0f / (1.0f + expf(-g0));
                float s1 = 1.0f / (1.0f + expf(-g1));
                __nv_bfloat162 o;
                o.x = __float2bfloat16_rn(d0 * s0);
                o.y = __float2bfloat16_rn(d1 * s1);
                *reinterpret_cast<__nv_bfloat162*>(out + (size_t)row * CH_ + oc) = o;
            }
        }
    }
}

// ---------------- standard bf16 GEMM (single-sync 3-stage) --------------------
#define ASTAGE 8192
#define BSTAGE 8192

template <int EPI>
__global__ __launch_bounds__(256, 2)
void gemm_bf16(const __nv_bfloat16* __restrict__ A, const __nv_bfloat16* __restrict__ W,
               int M, int N, int K,
               const float* __restrict__ bias,
               const float* __restrict__ aux, void* __restrict__ Cout) {
    __shared__ __nv_bfloat16 As[3 * 4096];
    __shared__ __nv_bfloat16 Bt[3 * 4096];

    const int tid  = threadIdx.x;
    const int warp = tid >> 5, lane = tid & 31;
    const int warpM = warp & 1;
    const int warpN = warp >> 1;
    const int bm = blockIdx.y * 128;
    const int bn = blockIdx.x * 128;

    const int r  = tid >> 2;
    const int c  = tid & 3;
    const int kb = tid >> 4;
    const int cb = tid & 15;
    const uint32_t sAb = smem_u32(As);
    const uint32_t sBb = smem_u32(Bt);
    const uint32_t aSt0 = sAb + (uint32_t)(r * 32 + ((c ^ ((r >> 1) & 3)) << 3)) * 2;
    const uint32_t aSt1 = sAb + (uint32_t)((r + 64) * 32 + ((c ^ ((r >> 1) & 3)) << 3)) * 2;
    const uint32_t bSt0 = sBb + (uint32_t)(kb * 128 + ((cb ^ (kb & 7)) << 3)) * 2;
    const uint32_t bSt1 = sBb + (uint32_t)((kb + 16) * 128 + ((cb ^ (kb & 7)) << 3)) * 2;

    const __nv_bfloat16* pa = A + (size_t)(bm + r) * K + c * 8;
    const __nv_bfloat16* pb = W + (size_t)kb * N + bn + cb * 8;
    const size_t paRow64 = (size_t)64 * K;
    const size_t pbRow16 = (size_t)16 * N;
    const size_t pbStep  = (size_t)32 * N;

    float acc[4][4][4];
#pragma unroll
    for (int a0 = 0; a0 < 4; a0++)
#pragma unroll
        for (int a1 = 0; a1 < 4; a1++)
#pragma unroll
            for (int a2 = 0; a2 < 4; a2++) acc[a0][a1][a2] = 0.f;

    const int l15 = lane & 15, hi = lane >> 4, l7 = lane & 7;
    int rowA[4], swzA[4];
#pragma unroll
    for (int mt = 0; mt < 4; mt++) {
        rowA[mt] = warpM * 64 + mt * 16 + l15;
        swzA[mt] = (rowA[mt] >> 1) & 3;
    }

    const int KT = K >> 5;

#pragma unroll
    for (int t = 0; t < 2; t++) {
        uint32_t ao = (uint32_t)t * ASTAGE;
        cp16(aSt0 + ao, pa + t * 32); cp16(aSt1 + ao, pa + t * 32 + paRow64);
        cp16(bSt0 + ao, pb + (size_t)t * pbStep); cp16(bSt1 + ao, pb + (size_t)t * pbStep + pbRow16);
        cp_commit();
    }

    int sL = 2, sC = 0;
    for (int kt = 0; kt < KT; kt++) {
        cp_wait1();
        __syncthreads();
        if (kt + 2 < KT) {
            uint32_t ao = (uint32_t)sL * ASTAGE;
            cp16(aSt0 + ao, pa + (kt + 2) * 32);
            cp16(aSt1 + ao, pa + (kt + 2) * 32 + paRow64);
            cp16(bSt0 + ao, pb + (size_t)(kt + 2) * pbStep);
            cp16(bSt1 + ao, pb + (size_t)(kt + 2) * pbStep + pbRow16);
        }
        cp_commit();

        const uint32_t sA = sAb + (uint32_t)sC * ASTAGE;
        const uint32_t sB = sBb + (uint32_t)sC * BSTAGE;
#pragma unroll
        for (int ks = 0; ks < 2; ks++) {
            uint32_t aF[4][4];
#pragma unroll
            for (int mt = 0; mt < 4; mt++) {
                uint32_t addr = sA + (uint32_t)(rowA[mt] * 32 +
                                  (((ks * 2 + hi) ^ swzA[mt]) << 3)) * 2;
                ldsm_x4(aF[mt], addr);
            }
            uint32_t bF[8];
#pragma unroll
            for (int half = 0; half < 2; half++) {
                int c0 = warpN * 4 + half * 2;
                uint32_t addr = sB + (uint32_t)((ks * 16 + l15) * 128 +
                                  (((c0 + hi) ^ l7) << 3)) * 2;
                ldsm_x4_t(&bF[half * 4], addr);
            }
#pragma unroll
            for (int mt = 0; mt < 4; mt++)
#pragma unroll
                for (int nt = 0; nt < 4; nt++)
                    mma16816(acc[mt][nt], aF[mt], &bF[nt * 2]);
        }
        sL = (sL == 2) ? 0 : sL + 1;
        sC = (sC == 2) ? 0 : sC + 1;
    }

    const int g = lane >> 2, tig = lane & 3;
#pragma unroll
    for (int mt = 0; mt < 4; mt++) {
#pragma unroll
        for (int nt = 0; nt < 4; nt++) {
            int col = bn + warpN * 32 + nt * 8 + tig * 2;
#pragma unroll
            for (int h = 0; h < 2; h++) {
                int row = bm + warpM * 64 + mt * 16 + g + h * 8;
                float v0 = acc[mt][nt][2 * h], v1 = acc[mt][nt][2 * h + 1];
                size_t oi = (size_t)row * N + col;
                if (EPI == 2) {
                    __nv_bfloat162 o;
                    o.x = __float2bfloat16_rn(gelu_tanh(v0 + bias[col]));
                    o.y = __float2bfloat16_rn(gelu_tanh(v1 + bias[col + 1]));
                    *reinterpret_cast<__nv_bfloat162*>((__nv_bfloat16*)Cout + oi) = o;
                } else {  // 4
                    float2 a2 = *reinterpret_cast<const float2*>(aux + oi);
                    float2 o = make_float2(0.5f * (v0 + bias[col]) + 0.5f * a2.x,
                                           0.5f * (v1 + bias[col + 1]) + 0.5f * a2.y);
                    *reinterpret_cast<float2*>((float*)Cout + oi) = o;
                }
            }
        }
    }
}

// ---------------- launch ------------------------------------------------------
static void* sym(const void* s) {
    void* p = nullptr;
    cudaGetSymbolAddress(&p, s);
    return p;
}

extern "C" void kernel_launch(void* const* d_in, const int* in_sizes, int n_in,
                              void* d_out, int out_size) {
    const float* x    = (const float*)d_in[0];
    const float* ln_g = (const float*)d_in[1];
    const float* ln_b = (const float*)d_in[2];
    const float* Wd   = (const float*)d_in[3];
    const float* bd   = (const float*)d_in[4];
    const float* Wg   = (const float*)d_in[5];
    const float* bg   = (const float*)d_in[6];
    const float* dw_w = (const float*)d_in[7];
    const float* dw_b = (const float*)d_in[8];
    const float* W1   = (const float*)d_in[9];
    const float* b1   = (const float*)d_in[10];
    const float* W2   = (const float*)d_in[11];
    const float* b2   = (const float*)d_in[12];
    // d_in[13..16] = Wq,bq,Wk,bk : dead (softmax over one key == 1)
    const float* Wv   = (const float*)d_in[17];
    const float* bv   = (const float*)d_in[18];
    const float* Wo   = (const float*)d_in[19];
    const float* bo   = (const float*)d_in[20];
    const float* Wu   = (const float*)d_in[21];
    const float* bu   = (const float*)d_in[22];
    const float* Wld  = (const float*)d_in[23];
    const float* Wlu  = (const float*)d_in[24];
    float* out = (float*)d_out;

    __nv_bfloat16* zW   = (__nv_bfloat16*)sym(g_z);
    __nv_bfloat16* uW   = (__nv_bfloat16*)sym(g_u);
    __nv_bfloat16* pW   = (__nv_bfloat16*)sym(g_p);
    __nv_bfloat16* Wglu = (__nv_bfloat16*)sym(g_Wglu);
    __nv_bfloat16* W1b  = (__nv_bfloat16*)sym(g_W1b);
    __nv_bfloat16* Wtb  = (__nv_bfloat16*)sym(g_Wtb);
    float* b1p = (float*)sym(g_b1p);
    float* bt  = (float*)sym(g_bt);

    // prep (3 launches)
    prepA<<<A_TOT / 256, 256>>>(Wv, Wo, bo, Wu, Wld, dw_w, dw_b, W1, b1, bv, bu, Wd, Wg);
    prepB<<<B_TOT / 256, 256>>>(W2, Wu, Wlu, b2, bu);
    prepC<<<68, 256>>>();

    // LN
    ln_kernel<<<B_, 256>>>(x, ln_g, ln_b, zW);

    // fused GLU GEMM  (launch #5 -> ncu -s 5 capture slot)
    cudaFuncSetAttribute(gemm_glu, cudaFuncAttributeMaxDynamicSharedMemorySize, 3 * GSTG);
    gemm_glu<<<dim3(2, B_ / 128), 512, 3 * GSTG>>>(zW, Wglu, bd, bg, uW);

    // gelu GEMM
    gemm_bf16<2><<<dim3(CH_ / 128, B_ / 128), 256>>>(uW, W1b, B_, CH_, CH_, b1p, nullptr, pW);

    // tail GEMM + residual
    gemm_bf16<4><<<dim3(C_ / 128, B_ / 128), 256>>>(pW, Wtb, B_, C_, CH_, bt, x, out);
}

// round 7
// speedup vs baseline: 3.8438x; 1.0818x over previous
#include <cuda_runtime.h>
#include <cuda_bf16.h>
#include <math.h>
#include <stdint.h>

#define B_  32768
#define C_  1024
#define CH_ 256
#define RANK_ 16

// ---------------- scratch (device globals; no allocation allowed) ------------
__device__ __nv_bfloat16 g_z [B_ * C_];     // LN output
__device__ __nv_bfloat16 g_u [B_ * CH_];    // GLU output
__device__ __nv_bfloat16 g_p [B_ * CH_];    // gelu output

__device__ __nv_bfloat16 g_Wglu[C_ * 512];  // [K=1024][512] interleaved 8d|8g per 16
__device__ __nv_bfloat16 g_W1b [CH_ * CH_]; // [K=256][N=256] dw-folded W1
__device__ __nv_bfloat16 g_Wtb [CH_ * C_];  // [K=256][N=1024] Wtail (bf16)

__device__ float g_fWvo[CH_ * CH_];
__device__ float g_fW23[CH_ * CH_];
__device__ float g_fT1 [CH_ * RANK_];
__device__ float g_fWuE[CH_ * C_];
__device__ float g_b1p[CH_], g_bvo[CH_], g_t16[RANK_], g_b23[CH_], g_buE[C_], g_bt[C_];

__device__ __forceinline__ float warp_sum(float s) {
#pragma unroll
    for (int o = 16; o; o >>= 1) s += __shfl_xor_sync(0xFFFFFFFFu, s, o);
    return s;
}

// ---------------- prepA: fWvo, fT1, b1p, bvo, t16, W1b, Wglu ------------------
#define A_FWVO 0
#define A_FT1  65536
#define A_B1P  196608
#define A_BVO  204800
#define A_T16  212992
#define A_W1B  213504
#define A_WGLU 279040
#define A_TOT  803328   // = 3138 * 256

__global__ void prepA(const float* __restrict__ Wv, const float* __restrict__ Wo,
                      const float* __restrict__ bo, const float* __restrict__ Wu,
                      const float* __restrict__ Wld, const float* __restrict__ dw_w,
                      const float* __restrict__ dw_b, const float* __restrict__ W1,
                      const float* __restrict__ b1, const float* __restrict__ bv,
                      const float* __restrict__ bu, const float* __restrict__ Wd,
                      const float* __restrict__ Wg) {
    int i = blockIdx.x * blockDim.x + threadIdx.x;
    if (i >= A_TOT) return;
    int lane = i & 31;
    if (i < A_FT1) {                       // fWvo = Wv @ Wo
        int r = i >> 8, c = i & 255;
        float s = 0.f;
#pragma unroll 8
        for (int k = 0; k < CH_; k++) s += Wv[r * CH_ + k] * Wo[k * CH_ + c];
        g_fWvo[i] = s;
    } else if (i < A_B1P) {                // fT1 = Wu @ Wld (warp-split K=1024)
        int w = (i - A_FT1) >> 5;
        int r = w >> 4, c = w & 15;
        float s = 0.f;
#pragma unroll
        for (int kk = 0; kk < 32; kk++) {
            int k = lane + kk * 32;
            s += Wu[r * C_ + k] * Wld[k * RANK_ + c];
        }
        s = warp_sum(s);
        if (lane == 0) g_fT1[w] = s;
    } else if (i < A_BVO) {                // b1p = dw_b @ W1 + b1
        int w = (i - A_B1P) >> 5;
        float s = 0.f;
#pragma unroll
        for (int kk = 0; kk < 8; kk++) {
            int k = lane + kk * 32;
            s += dw_b[k] * W1[k * CH_ + w];
        }
        s = warp_sum(s);
        if (lane == 0) g_b1p[w] = s + b1[w];
    } else if (i < A_T16) {                // bvo = bv @ Wo + bo
        int w = (i - A_BVO) >> 5;
        float s = 0.f;
#pragma unroll
        for (int kk = 0; kk < 8; kk++) {
            int k = lane + kk * 32;
            s += bv[k] * Wo[k * CH_ + w];
        }
        s = warp_sum(s);
        if (lane == 0) g_bvo[w] = s + bo[w];
    } else if (i < A_W1B) {                // t16 = bu @ Wld
        int w = (i - A_T16) >> 5;
        float s = 0.f;
#pragma unroll
        for (int kk = 0; kk < 32; kk++) {
            int k = lane + kk * 32;
            s += bu[k] * Wld[k * RANK_ + w];
        }
        s = warp_sum(s);
        if (lane == 0) g_t16[w] = s;
    } else if (i < A_WGLU) {               // W1b = diag(dw_w) @ W1 (bf16)
        int j = i - A_W1B;
        int k = j >> 8, n = j & 255;
        g_W1b[j] = __float2bfloat16_rn(dw_w[k] * W1[k * CH_ + n]);
    } else {                               // Wglu interleaved (bf16)
        int j = i - A_WGLU;
        int k = j >> 9, F = j & 511;
        int grp = F >> 4, wi = F & 15;
        int col = grp * 8 + (wi & 7);
        float v = (wi < 8) ? Wd[k * CH_ + col] : Wg[k * CH_ + col];
        g_Wglu[j] = __float2bfloat16_rn(v);
    }
}

// ---------------- prepB: fW23, fWuE, b23, buE ---------------------------------
#define B_FW23 0
#define B_FWUE 65536
#define B_B23  327680
#define B_BUE  335872
#define B_TOT  336896

__global__ void prepB(const float* __restrict__ W2, const float* __restrict__ Wu,
                      const float* __restrict__ Wlu, const float* __restrict__ b2,
                      const float* __restrict__ bu) {
    int i = blockIdx.x * blockDim.x + threadIdx.x;
    if (i >= B_TOT) return;
    int lane = i & 31;
    if (i < B_FWUE) {                      // fW23 = W2 @ fWvo
        int r = i >> 8, c = i & 255;
        float s = 0.f;
#pragma unroll 8
        for (int k = 0; k < CH_; k++) s += W2[r * CH_ + k] * g_fWvo[k * CH_ + c];
        g_fW23[i] = s;
    } else if (i < B_B23) {                // fWuE = Wu + fT1 @ Wlu
        int j = i - B_FWUE;
        int r = j >> 10, c = j & 1023;
        float s = Wu[j];
#pragma unroll
        for (int k = 0; k < RANK_; k++) s += g_fT1[r * RANK_ + k] * Wlu[k * C_ + c];
        g_fWuE[j] = s;
    } else if (i < B_BUE) {                // b23 = b2 @ fWvo + bvo
        int w = (i - B_B23) >> 5;
        float s = 0.f;
#pragma unroll
        for (int kk = 0; kk < 8; kk++) {
            int k = lane + kk * 32;
            s += b2[k] * g_fWvo[k * CH_ + w];
        }
        s = warp_sum(s);
        if (lane == 0) g_b23[w] = s + g_bvo[w];
    } else {                               // buE = bu + t16 @ Wlu
        int j = i - B_BUE;
        float s = bu[j];
#pragma unroll
        for (int k = 0; k < RANK_; k++) s += g_t16[k] * Wlu[k * C_ + j];
        g_buE[j] = s;
    }
}

// ---------------- prepC: Wtb = bf16(fW23 @ fWuE), bt --------------------------
__global__ __launch_bounds__(256)
void prepC() {
    int bid = blockIdx.x;
    int tid = threadIdx.x;
    if (bid < 64) {
        __shared__ float As[64][33];
        __shared__ float Bs[32][65];
        int by = bid >> 4, bx = bid & 15;
        int ty = tid >> 4, tx = tid & 15;
        float acc[4][4];
#pragma unroll
        for (int a = 0; a < 4; a++)
#pragma unroll
            for (int b = 0; b < 4; b++) acc[a][b] = 0.f;
        for (int kc = 0; kc < 8; kc++) {
#pragma unroll
            for (int j = 0; j < 8; j++) {
                int e = tid + j * 256;
                int m = e >> 5, k = e & 31;
                As[m][k] = g_fW23[(by * 64 + m) * CH_ + kc * 32 + k];
            }
#pragma unroll
            for (int j = 0; j < 8; j++) {
                int e = tid + j * 256;
                int k = e >> 6, n = e & 63;
                Bs[k][n] = g_fWuE[(kc * 32 + k) * C_ + bx * 64 + n];
            }
            __syncthreads();
#pragma unroll
            for (int k = 0; k < 32; k++) {
                float a0 = As[ty * 4 + 0][k], a1 = As[ty * 4 + 1][k];
                float a2 = As[ty * 4 + 2][k], a3 = As[ty * 4 + 3][k];
                float b0 = Bs[k][tx * 4 + 0], b1 = Bs[k][tx * 4 + 1];
                float b2 = Bs[k][tx * 4 + 2], b3 = Bs[k][tx * 4 + 3];
                acc[0][0] += a0 * b0; acc[0][1] += a0 * b1; acc[0][2] += a0 * b2; acc[0][3] += a0 * b3;
                acc[1][0] += a1 * b0; acc[1][1] += a1 * b1; acc[1][2] += a1 * b2; acc[1][3] += a1 * b3;
                acc[2][0] += a2 * b0; acc[2][1] += a2 * b1; acc[2][2] += a2 * b2; acc[2][3] += a2 * b3;
                acc[3][0] += a3 * b0; acc[3][1] += a3 * b1; acc[3][2] += a3 * b2; acc[3][3] += a3 * b3;
            }
            __syncthreads();
        }
#pragma unroll
        for (int a = 0; a < 4; a++) {
            int row = by * 64 + ty * 4 + a;
#pragma unroll
            for (int b = 0; b < 4; b++) {
                int col = bx * 64 + tx * 4 + b;
                g_Wtb[row * C_ + col] = __float2bfloat16_rn(acc[a][b]);
            }
        }
    } else {
        int w = (bid - 64) * 8 + (tid >> 5);
        int lane = tid & 31;
        for (int jj = 0; jj < 32; jj++) {
            int j = w * 32 + jj;
            float s = 0.f;
#pragma unroll
            for (int kk = 0; kk < 8; kk++) {
                int k = lane + kk * 32;
                s += g_b23[k] * g_fWuE[k * C_ + j];
            }
            s = warp_sum(s);
            if (lane == 0) g_bt[j] = s + g_buE[j];
        }
    }
}

// ---------------- LayerNorm: warp-per-row, no barriers ------------------------
__global__ __launch_bounds__(256)
void ln_kernel(const float* __restrict__ x, const float* __restrict__ gamma,
               const float* __restrict__ beta, __nv_bfloat16* __restrict__ z) {
    const int w = (blockIdx.x * 256 + threadIdx.x) >> 5;   // global warp == row
    const int lane = threadIdx.x & 31;
    const float4* px = (const float4*)(x + (size_t)w * C_);
    float4 v[8];
#pragma unroll
    for (int j = 0; j < 8; j++) v[j] = px[lane + j * 32];
    float s = 0.f, ss = 0.f;
#pragma unroll
    for (int j = 0; j < 8; j++) {
        s  += v[j].x + v[j].y + v[j].z + v[j].w;
        ss += v[j].x * v[j].x + v[j].y * v[j].y + v[j].z * v[j].z + v[j].w * v[j].w;
    }
    s  = warp_sum(s);
    ss = warp_sum(ss);
    float mean = s * (1.f / C_);
    float var  = ss * (1.f / C_) - mean * mean;
    float rstd = rsqrtf(var + 1e-5f);
    uint2* pz = (uint2*)(z + (size_t)w * C_);
    const float4* pg = (const float4*)gamma;
    const float4* pb = (const float4*)beta;
#pragma unroll
    for (int j = 0; j < 8; j++) {
        float4 gm = pg[lane + j * 32];
        float4 bt = pb[lane + j * 32];
        union { __nv_bfloat16 h[4]; uint2 u; } pk;
        pk.h[0] = __float2bfloat16_rn((v[j].x - mean) * rstd * gm.x + bt.x);
        pk.h[1] = __float2bfloat16_rn((v[j].y - mean) * rstd * gm.y + bt.y);
        pk.h[2] = __float2bfloat16_rn((v[j].z - mean) * rstd * gm.z + bt.z);
        pk.h[3] = __float2bfloat16_rn((v[j].w - mean) * rstd * gm.w + bt.w);
        pz[lane + j * 32] = pk.u;
    }
}

// ---------------- shared GEMM primitives -------------------------------------
__device__ __forceinline__ uint32_t smem_u32(const void* p) {
    return (uint32_t)__cvta_generic_to_shared(p);
}
__device__ __forceinline__ void cp16(uint32_t d, const void* s) {
    asm volatile("cp.async.cg.shared.global [%0], [%1], 16;\n" :: "r"(d), "l"(s));
}
__device__ __forceinline__ void cp_commit() { asm volatile("cp.async.commit_group;\n"); }
__device__ __forceinline__ void cp_wait1()  { asm volatile("cp.async.wait_group 1;\n"); }
__device__ __forceinline__ void ldsm_x4(uint32_t* r, uint32_t a) {
    asm volatile("ldmatrix.sync.aligned.m8n8.x4.shared.b16 {%0,%1,%2,%3}, [%4];\n"
                 : "=r"(r[0]), "=r"(r[1]), "=r"(r[2]), "=r"(r[3]) : "r"(a));
}
__device__ __forceinline__ void ldsm_x4_t(uint32_t* r, uint32_t a) {
    asm volatile("ldmatrix.sync.aligned.m8n8.x4.trans.shared.b16 {%0,%1,%2,%3}, [%4];\n"
                 : "=r"(r[0]), "=r"(r[1]), "=r"(r[2]), "=r"(r[3]) : "r"(a));
}
__device__ __forceinline__ void mma16816(float* c, const uint32_t* a, const uint32_t* b) {
    asm volatile(
        "mma.sync.aligned.m16n8k16.row.col.f32.bf16.bf16.f32 "
        "{%0,%1,%2,%3}, {%4,%5,%6,%7}, {%8,%9}, {%0,%1,%2,%3};\n"
        : "+f"(c[0]), "+f"(c[1]), "+f"(c[2]), "+f"(c[3])
        : "r"(a[0]), "r"(a[1]), "r"(a[2]), "r"(a[3]), "r"(b[0]), "r"(b[1]));
}
__device__ __forceinline__ float gelu_tanh(float t) {
    float t3 = t * t * t;
    return 0.5f * t * (1.0f + tanhf(0.7978845608028654f * (t + 0.044715f * t3)));
}

// ---------------- fused GLU GEMM (BK=64, 3-stage, single-sync) ----------------
// A tile 128x64 (16KB), B tile 64x256-fused (32KB); stage 48KB; 512 threads.
#define GSTG 49152
#define GB_OFF 16384

__global__ __launch_bounds__(512)
void gemm_glu(const __nv_bfloat16* __restrict__ A, const __nv_bfloat16* __restrict__ W,
              const float* __restrict__ bd, const float* __restrict__ bg,
              __nv_bfloat16* __restrict__ out) {
    extern __shared__ __align__(1024) char dsm[];
    const int tid  = threadIdx.x;
    const int warp = tid >> 5, lane = tid & 31;
    const int warpM = warp & 1;
    const int warpN = warp >> 1;
    const int bm  = blockIdx.y * 128;
    const int bnf = blockIdx.x * 256;
    const uint32_t sb = smem_u32(dsm);

    // A stores: 2 chunks/thread. r = (tid>>3)+i*64, c = tid&7
    const int ra = tid >> 3, ca = tid & 7;
    uint32_t aSt[2];
    const __nv_bfloat16* pA[2];
#pragma unroll
    for (int i = 0; i < 2; i++) {
        int r = ra + i * 64;
        aSt[i] = (uint32_t)(r * 64 + ((ca ^ (r & 7)) << 3)) * 2;
        pA[i] = A + (size_t)(bm + r) * C_ + ca * 8;
    }
    // B stores: 4 chunks/thread. kb = (tid>>5)+i*16, cb = tid&31
    const int kb0 = tid >> 5, cb = tid & 31;
    uint32_t bSt[4];
    const __nv_bfloat16* pB[4];
#pragma unroll
    for (int i = 0; i < 4; i++) {
        int kb = kb0 + i * 16;
        bSt[i] = (uint32_t)(kb * 256 + ((cb >> 3) << 6) + (((cb & 7) ^ (kb & 7)) << 3)) * 2;
        pB[i] = W + (size_t)kb * 512 + bnf + cb * 8;
    }
    const size_t pbStep = (size_t)64 * 512;

    float acc[4][4][4];
#pragma unroll
    for (int a0 = 0; a0 < 4; a0++)
#pragma unroll
        for (int a1 = 0; a1 < 4; a1++)
#pragma unroll
            for (int a2 = 0; a2 < 4; a2++) acc[a0][a1][a2] = 0.f;

    const int l15 = lane & 15, hi = lane >> 4, l7 = lane & 7;
    int rowA[4];
#pragma unroll
    for (int mt = 0; mt < 4; mt++) rowA[mt] = warpM * 64 + mt * 16 + l15;

    const int KT = C_ >> 6;   // 16

#pragma unroll
    for (int t = 0; t < 2; t++) {
        uint32_t base = sb + t * GSTG;
#pragma unroll
        for (int i = 0; i < 2; i++) cp16(base + aSt[i], pA[i] + t * 64);
#pragma unroll
        for (int i = 0; i < 4; i++) cp16(base + GB_OFF + bSt[i], pB[i] + (size_t)t * pbStep);
        cp_commit();
    }

    int sL = 2, sC = 0;
    for (int kt = 0; kt < KT; kt++) {
        cp_wait1();
        __syncthreads();
        if (kt + 2 < KT) {
            uint32_t base = sb + sL * GSTG;
#pragma unroll
            for (int i = 0; i < 2; i++) cp16(base + aSt[i], pA[i] + (kt + 2) * 64);
#pragma unroll
            for (int i = 0; i < 4; i++) cp16(base + GB_OFF + bSt[i], pB[i] + (size_t)(kt + 2) * pbStep);
        }
        cp_commit();

        const uint32_t sA = sb + sC * GSTG;
        const uint32_t sB = sA + GB_OFF;
#pragma unroll
        for (int ks = 0; ks < 4; ks++) {
            uint32_t aF[4][4];
#pragma unroll
            for (int mt = 0; mt < 4; mt++) {
                uint32_t addr = sA + (uint32_t)(rowA[mt] * 64 +
                                  (((ks * 2 + hi) ^ (rowA[mt] & 7)) << 3)) * 2;
                ldsm_x4(aF[mt], addr);
            }
            uint32_t bF[8];
#pragma unroll
            for (int half = 0; half < 2; half++) {
                int q = warpN * 4 + half * 2 + hi;
                uint32_t addr = sB + (uint32_t)((ks * 16 + l15) * 256 +
                                  ((q >> 3) << 6) + (((q & 7) ^ l7) << 3)) * 2;
                ldsm_x4_t(&bF[half * 4], addr);
            }
#pragma unroll
            for (int mt = 0; mt < 4; mt++)
#pragma unroll
                for (int nt = 0; nt < 4; nt++)
                    mma16816(acc[mt][nt], aF[mt], &bF[nt * 2]);
        }
        sL = (sL == 2) ? 0 : sL + 1;
        sC = (sC == 2) ? 0 : sC + 1;
    }

    const int g = lane >> 2, tig = lane & 3;
#pragma unroll
    for (int mt = 0; mt < 4; mt++) {
#pragma unroll
        for (int j = 0; j < 2; j++) {
            int F = bnf + warpN * 32 + j * 16 + tig * 2;
            int oc = ((F >> 4) << 3) + (F & 7);
            float bdc0 = bd[oc], bdc1 = bd[oc + 1];
            float bgc0 = bg[oc], bgc1 = bg[oc + 1];
#pragma unroll
            for (int h = 0; h < 2; h++) {
                int row = bm + warpM * 64 + mt * 16 + g + h * 8;
                float d0 = acc[mt][2 * j][2 * h]     + bdc0;
                float d1 = acc[mt][2 * j][2 * h + 1] + bdc1;
                float g0 = acc[mt][2 * j + 1][2 * h]     + bgc0;
                float g1 = acc[mt][2 * j + 1][2 * h + 1] + bgc1;
                float s0 = 1.0f / (1.0f + expf(-g0));
                float s1 = 1.0f / (1.0f + expf(-g1));
                __nv_bfloat162 o;
                o.x = __float2bfloat16_rn(d0 * s0);
                o.y = __float2bfloat16_rn(d1 * s1);
                *reinterpret_cast<__nv_bfloat162*>(out + (size_t)row * CH_ + oc) = o;
            }
        }
    }
}

// ---------------- standard bf16 GEMM (BK=64, 3-stage, single-sync) ------------
// A tile 128x64 (16KB), B tile 64x128 (16KB); stage 32KB; 256 threads, occ 2.
#define SSTG 32768
#define SB_OFF 16384

template <int EPI>
__global__ __launch_bounds__(256, 2)
void gemm_bf16(const __nv_bfloat16* __restrict__ A, const __nv_bfloat16* __restrict__ W,
               int M, int N, int K,
               const float* __restrict__ bias,
               const float* __restrict__ aux, void* __restrict__ Cout) {
    extern __shared__ __align__(1024) char dsm[];
    const int tid  = threadIdx.x;
    const int warp = tid >> 5, lane = tid & 31;
    const int warpM = warp & 1;
    const int warpN = warp >> 1;
    const int bm = blockIdx.y * 128;
    const int bn = blockIdx.x * 128;
    const uint32_t sb = smem_u32(dsm);

    // A stores: 4 chunks/thread
    const int ra = tid >> 3, ca = tid & 7;
    uint32_t aSt[4];
    const __nv_bfloat16* pA[4];
#pragma unroll
    for (int i = 0; i < 4; i++) {
        int r = ra + i * 32;
        aSt[i] = (uint32_t)(r * 64 + ((ca ^ (r & 7)) << 3)) * 2;
        pA[i] = A + (size_t)(bm + r) * K + ca * 8;
    }
    // B stores: 4 chunks/thread
    const int kb0 = tid >> 4, cbx = tid & 15;
    uint32_t bSt[4];
    const __nv_bfloat16* pB[4];
#pragma unroll
    for (int i = 0; i < 4; i++) {
        int kb = kb0 + i * 16;
        bSt[i] = (uint32_t)(kb * 128 + ((cbx >> 3) << 6) + (((cbx & 7) ^ (kb & 7)) << 3)) * 2;
        pB[i] = W + (size_t)kb * N + bn + cbx * 8;
    }
    const size_t pbStep = (size_t)64 * N;

    float acc[4][4][4];
#pragma unroll
    for (int a0 = 0; a0 < 4; a0++)
#pragma unroll
        for (int a1 = 0; a1 < 4; a1++)
#pragma unroll
            for (int a2 = 0; a2 < 4; a2++) acc[a0][a1][a2] = 0.f;

    const int l15 = lane & 15, hi = lane >> 4, l7 = lane & 7;
    int rowA[4];
#pragma unroll
    for (int mt = 0; mt < 4; mt++) rowA[mt] = warpM * 64 + mt * 16 + l15;

    const int KT = K >> 6;

#pragma unroll
    for (int t = 0; t < 2; t++) {
        uint32_t base = sb + t * SSTG;
#pragma unroll
        for (int i = 0; i < 4; i++) cp16(base + aSt[i], pA[i] + t * 64);
#pragma unroll
        for (int i = 0; i < 4; i++) cp16(base + SB_OFF + bSt[i], pB[i] + (size_t)t * pbStep);
        cp_commit();
    }

    int sL = 2, sC = 0;
    for (int kt = 0; kt < KT; kt++) {
        cp_wait1();
        __syncthreads();
        if (kt + 2 < KT) {
            uint32_t base = sb + sL * SSTG;
#pragma unroll
            for (int i = 0; i < 4; i++) cp16(base + aSt[i], pA[i] + (kt + 2) * 64);
#pragma unroll
            for (int i = 0; i < 4; i++) cp16(base + SB_OFF + bSt[i], pB[i] + (size_t)(kt + 2) * pbStep);
        }
        cp_commit();

        const uint32_t sA = sb + sC * SSTG;
        const uint32_t sB = sA + SB_OFF;
#pragma unroll
        for (int ks = 0; ks < 4; ks++) {
            uint32_t aF[4][4];
#pragma unroll
            for (int mt = 0; mt < 4; mt++) {
                uint32_t addr = sA + (uint32_t)(rowA[mt] * 64 +
                                  (((ks * 2 + hi) ^ (rowA[mt] & 7)) << 3)) * 2;
                ldsm_x4(aF[mt], addr);
            }
            uint32_t bF[8];
#pragma unroll
            for (int half = 0; half < 2; half++) {
                int c0 = warpN * 4 + half * 2;
                uint32_t addr = sB + (uint32_t)((ks * 16 + l15) * 128 +
                                  (((c0 + hi) ^ l7) << 3)) * 2;
                ldsm_x4_t(&bF[half * 4], addr);
            }
#pragma unroll
            for (int mt = 0; mt < 4; mt++)
#pragma unroll
                for (int nt = 0; nt < 4; nt++)
                    mma16816(acc[mt][nt], aF[mt], &bF[nt * 2]);
        }
        sL = (sL == 2) ? 0 : sL + 1;
        sC = (sC == 2) ? 0 : sC + 1;
    }

    const int g = lane >> 2, tig = lane & 3;
#pragma unroll
    for (int mt = 0; mt < 4; mt++) {
#pragma unroll
        for (int nt = 0; nt < 4; nt++) {
            int col = bn + warpN * 32 + nt * 8 + tig * 2;
#pragma unroll
            for (int h = 0; h < 2; h++) {
                int row = bm + warpM * 64 + mt * 16 + g + h * 8;
                float v0 = acc[mt][nt][2 * h], v1 = acc[mt][nt][2 * h + 1];
                size_t oi = (size_t)row * N + col;
                if (EPI == 2) {
                    __nv_bfloat162 o;
                    o.x = __float2bfloat16_rn(gelu_tanh(v0 + bias[col]));
                    o.y = __float2bfloat16_rn(gelu_tanh(v1 + bias[col + 1]));
                    *reinterpret_cast<__nv_bfloat162*>((__nv_bfloat16*)Cout + oi) = o;
                } else {  // 4
                    float2 a2 = *reinterpret_cast<const float2*>(aux + oi);
                    float2 o = make_float2(0.5f * (v0 + bias[col]) + 0.5f * a2.x,
                                           0.5f * (v1 + bias[col + 1]) + 0.5f * a2.y);
                    *reinterpret_cast<float2*>((float*)Cout + oi) = o;
                }
            }
        }
    }
}

// ---------------- launch ------------------------------------------------------
static void* sym(const void* s) {
    void* p = nullptr;
    cudaGetSymbolAddress(&p, s);
    return p;
}

extern "C" void kernel_launch(void* const* d_in, const int* in_sizes, int n_in,
                              void* d_out, int out_size) {
    const float* x    = (const float*)d_in[0];
    const float* ln_g = (const float*)d_in[1];
    const float* ln_b = (const float*)d_in[2];
    const float* Wd   = (const float*)d_in[3];
    const float* bd   = (const float*)d_in[4];
    const float* Wg   = (const float*)d_in[5];
    const float* bg   = (const float*)d_in[6];
    const float* dw_w = (const float*)d_in[7];
    const float* dw_b = (const float*)d_in[8];
    const float* W1   = (const float*)d_in[9];
    const float* b1   = (const float*)d_in[10];
    const float* W2   = (const float*)d_in[11];
    const float* b2   = (const float*)d_in[12];
    // d_in[13..16] = Wq,bq,Wk,bk : dead (softmax over one key == 1)
    const float* Wv   = (const float*)d_in[17];
    const float* bv   = (const float*)d_in[18];
    const float* Wo   = (const float*)d_in[19];
    const float* bo   = (const float*)d_in[20];
    const float* Wu   = (const float*)d_in[21];
    const float* bu   = (const float*)d_in[22];
    const float* Wld  = (const float*)d_in[23];
    const float* Wlu  = (const float*)d_in[24];
    float* out = (float*)d_out;

    __nv_bfloat16* zW   = (__nv_bfloat16*)sym(g_z);
    __nv_bfloat16* uW   = (__nv_bfloat16*)sym(g_u);
    __nv_bfloat16* pW   = (__nv_bfloat16*)sym(g_p);
    __nv_bfloat16* Wglu = (__nv_bfloat16*)sym(g_Wglu);
    __nv_bfloat16* W1b  = (__nv_bfloat16*)sym(g_W1b);
    __nv_bfloat16* Wtb  = (__nv_bfloat16*)sym(g_Wtb);
    float* b1p = (float*)sym(g_b1p);
    float* bt  = (float*)sym(g_bt);

    cudaFuncSetAttribute(gemm_glu, cudaFuncAttributeMaxDynamicSharedMemorySize, 3 * GSTG);
    cudaFuncSetAttribute(gemm_bf16<2>, cudaFuncAttributeMaxDynamicSharedMemorySize, 3 * SSTG);
    cudaFuncSetAttribute(gemm_bf16<4>, cudaFuncAttributeMaxDynamicSharedMemorySize, 3 * SSTG);

    // 1,2: prep (Wglu ready after prepA)
    prepA<<<A_TOT / 256, 256>>>(Wv, Wo, bo, Wu, Wld, dw_w, dw_b, W1, b1, bv, bu, Wd, Wg);
    prepB<<<B_TOT / 256, 256>>>(W2, Wu, Wlu, b2, bu);

    // 3: LN
    ln_kernel<<<B_ / 8, 256>>>(x, ln_g, ln_b, zW);

    // 4: fused GLU GEMM  (profiler capture slot)
    gemm_glu<<<dim3(2, B_ / 128), 512, 3 * GSTG>>>(zW, Wglu, bd, bg, uW);

    // 5: prepC (needs prepB only; must precede tail)
    prepC<<<68, 256>>>();

    // 6: gelu GEMM
    gemm_bf16<2><<<dim3(CH_ / 128, B_ / 128), 256, 3 * SSTG>>>(uW, W1b, B_, CH_, CH_, b1p, nullptr, pW);

    // 7: tail GEMM + residual
    gemm_bf16<4><<<dim3(C_ / 128, B_ / 128), 256, 3 * SSTG>>>(pW, Wtb, B_, C_, CH_, bt, x, out);
}